// round 1
// baseline (speedup 1.0000x reference)
#include <cuda_runtime.h>
#include <cstdint>
#include <cstddef>

// Problem constants
#define PB 8
#define PS 1024
#define PE 1024
#define PH 16
#define PD 64
#define PM (PB * PS)        // 8192 GEMM rows
#define PBH (PB * PH)       // 128 (b,h) pairs

// ---------------------------------------------------------------------------
// Scratch (static __device__ — allocation-free per harness rules)
// q/k/v projections, each (B,S,E) fp32 = 32MB; attention output same size.
// ---------------------------------------------------------------------------
__device__ float g_q[PB * PS * PE];
__device__ float g_k[PB * PS * PE];
__device__ float g_v[PB * PS * PE];
__device__ float g_o[PB * PS * PE];

// ---------------------------------------------------------------------------
// SGEMM 128x128x8, 256 threads, 8x8 micro-tile, fp32.
// PERM=true reads A as the (B,H,S,D)->(B,S,E) permutation of g_o:
//   A(m = b*S+s, k = h*64+d) = g_o[((b*16+h)*1024 + s)*64 + d]
// ---------------------------------------------------------------------------
#define BM 128
#define BN 128
#define BK 8

template <bool PERM>
__device__ __forceinline__ void sgemm_body(const float* __restrict__ A,
                                           const float* __restrict__ W,
                                           const float* __restrict__ bias,
                                           float* __restrict__ C)
{
    constexpr int N = PE;
    constexpr int K = PE;

    __shared__ float As[BK][BM];   // A stored transposed: As[k][m]
    __shared__ float Bs[BK][BN];

    const int tid = threadIdx.x;                 // 256 threads
    const int block_row = blockIdx.y * BM;
    const int block_col = blockIdx.x * BN;

    // A tile loader: 128 rows x 8 cols -> one float4 per thread
    const int a_r = tid >> 1;                    // 0..127
    const int a_c = (tid & 1) << 2;              // 0 or 4
    // B tile loader: 8 rows x 128 cols -> one float4 per thread
    const int b_r = tid >> 5;                    // 0..7
    const int b_c = (tid & 31) << 2;             // 0..124

    const int ty = tid >> 4;                     // 0..15 -> rows ty*8..+7
    const int tx = tid & 15;                     // 0..15 -> cols tx*8..+7

    float acc[8][8];
#pragma unroll
    for (int i = 0; i < 8; i++)
#pragma unroll
        for (int j = 0; j < 8; j++) acc[i][j] = 0.0f;

    for (int kt = 0; kt < K; kt += BK) {
        float4 av;
        if (PERM) {
            const int gm = block_row + a_r;
            const int gk = kt + a_c;             // multiple of 4, stays in one 64-block
            const int bb = gm >> 10, ss = gm & 1023;
            const int hh = gk >> 6, dd = gk & 63;
            av = *reinterpret_cast<const float4*>(
                &A[(((size_t)(bb * PH + hh)) * PS + ss) * PD + dd]);
        } else {
            av = *reinterpret_cast<const float4*>(
                &A[(size_t)(block_row + a_r) * K + kt + a_c]);
        }
        const float4 bv = *reinterpret_cast<const float4*>(
            &W[(size_t)(kt + b_r) * N + block_col + b_c]);

        __syncthreads();  // previous iteration's compute done before overwrite
        As[a_c + 0][a_r] = av.x;
        As[a_c + 1][a_r] = av.y;
        As[a_c + 2][a_r] = av.z;
        As[a_c + 3][a_r] = av.w;
        *reinterpret_cast<float4*>(&Bs[b_r][b_c]) = bv;
        __syncthreads();

#pragma unroll
        for (int kk = 0; kk < BK; kk++) {
            const float4 a0 = *reinterpret_cast<const float4*>(&As[kk][ty * 8]);
            const float4 a1 = *reinterpret_cast<const float4*>(&As[kk][ty * 8 + 4]);
            const float4 b0 = *reinterpret_cast<const float4*>(&Bs[kk][tx * 8]);
            const float4 b1 = *reinterpret_cast<const float4*>(&Bs[kk][tx * 8 + 4]);
            const float ra[8] = {a0.x, a0.y, a0.z, a0.w, a1.x, a1.y, a1.z, a1.w};
            const float rb[8] = {b0.x, b0.y, b0.z, b0.w, b1.x, b1.y, b1.z, b1.w};
#pragma unroll
            for (int i = 0; i < 8; i++)
#pragma unroll
                for (int j = 0; j < 8; j++) acc[i][j] += ra[i] * rb[j];
        }
    }

#pragma unroll
    for (int i = 0; i < 8; i++) {
        const size_t gr = (size_t)(block_row + ty * 8 + i);
#pragma unroll
        for (int j = 0; j < 8; j += 4) {
            const int gc = block_col + tx * 8 + j;
            float4 v;
            v.x = acc[i][j + 0];
            v.y = acc[i][j + 1];
            v.z = acc[i][j + 2];
            v.w = acc[i][j + 3];
            if (bias) {
                v.x += bias[gc + 0];
                v.y += bias[gc + 1];
                v.z += bias[gc + 2];
                v.w += bias[gc + 3];
            }
            *reinterpret_cast<float4*>(&C[gr * N + gc]) = v;
        }
    }
}

__global__ __launch_bounds__(256) void qkv_gemm(const float* __restrict__ X,
                                                const float* __restrict__ Wq,
                                                const float* __restrict__ Wk,
                                                const float* __restrict__ Wv)
{
    const float* W = (blockIdx.z == 0) ? Wq : (blockIdx.z == 1) ? Wk : Wv;
    float* C = (blockIdx.z == 0) ? g_q : (blockIdx.z == 1) ? g_k : g_v;
    sgemm_body<false>(X, W, nullptr, C);
}

__global__ __launch_bounds__(256) void out_gemm(const float* __restrict__ Wo,
                                                const float* __restrict__ bo,
                                                float* __restrict__ out)
{
    sgemm_body<true>(g_o, Wo, bo, out);
}

// ---------------------------------------------------------------------------
// Flash attention fp32. grid (S/64=16, B*H=128), 128 threads/block.
// Br=Bc=64. Per-thread micro-tile: 4 rows x 8 cols. Smem operands stored
// transposed (Qt[k][r], Kt[k][c]) so every compute read is a broadcast-friendly
// LDS.128. P tile reuses Kt's buffer between syncs.
// Dynamic smem: 3 * 64*68 floats = 52224 bytes.
// ---------------------------------------------------------------------------
#define ATT_SMEM_FLOATS (3 * 64 * 68)

__global__ __launch_bounds__(128) void flash_attn()
{
    extern __shared__ float sm[];
    float* Qt  = sm;                 // [64][68]  Qt[d][qrow], pre-scaled
    float* KPt = sm + 64 * 68;       // [64][68]  Kt[d][krow], then Pt[k][qrow]
    float* Vs  = sm + 2 * 64 * 68;   // [64][68]  Vs[krow][d]

    const int tid = threadIdx.x;
    const int bh  = blockIdx.y;
    const int q0  = blockIdx.x * 64;

    const float* Q  = g_q + (size_t)bh * PS * PD;
    const float* Kg = g_k + (size_t)bh * PS * PD;
    const float* Vg = g_v + (size_t)bh * PS * PD;
    const float scale = 0.03125f;    // E^-0.5 = 1/32 (reference quirk)

    const int ty = tid >> 3;         // 0..15 -> rows r0..r0+3
    const int tx = tid & 7;          // 0..7  -> cols c0..c0+7
    const int r0 = ty * 4;
    const int c0 = tx * 8;

    // Load Q tile transposed + pre-scaled
    for (int i = tid; i < 64 * 16; i += 128) {
        const int row = i >> 4;
        const int c4  = (i & 15) << 2;
        const float4 qv = *reinterpret_cast<const float4*>(&Q[(q0 + row) * PD + c4]);
        Qt[(c4 + 0) * 68 + row] = qv.x * scale;
        Qt[(c4 + 1) * 68 + row] = qv.y * scale;
        Qt[(c4 + 2) * 68 + row] = qv.z * scale;
        Qt[(c4 + 3) * 68 + row] = qv.w * scale;
    }

    float m_i[4], l_i[4], O[4][8];
#pragma unroll
    for (int i = 0; i < 4; i++) {
        m_i[i] = -1e30f;
        l_i[i] = 0.0f;
#pragma unroll
        for (int j = 0; j < 8; j++) O[i][j] = 0.0f;
    }

    for (int t = 0; t < 16; t++) {
        const int k0 = t * 64;
        __syncthreads();  // previous tile's P/V reads complete (also covers Q load)

        // Load K transposed + V straight
        for (int i = tid; i < 64 * 16; i += 128) {
            const int row = i >> 4;
            const int c4  = (i & 15) << 2;
            const float4 kv = *reinterpret_cast<const float4*>(&Kg[(k0 + row) * PD + c4]);
            KPt[(c4 + 0) * 68 + row] = kv.x;
            KPt[(c4 + 1) * 68 + row] = kv.y;
            KPt[(c4 + 2) * 68 + row] = kv.z;
            KPt[(c4 + 3) * 68 + row] = kv.w;
            const float4 vv = *reinterpret_cast<const float4*>(&Vg[(k0 + row) * PD + c4]);
            *reinterpret_cast<float4*>(&Vs[row * 68 + c4]) = vv;
        }
        __syncthreads();

        // S = (Q*scale) K^T : 64x64, micro 4x8
        float s[4][8];
#pragma unroll
        for (int i = 0; i < 4; i++)
#pragma unroll
            for (int j = 0; j < 8; j++) s[i][j] = 0.0f;

#pragma unroll 8
        for (int kk = 0; kk < 64; kk++) {
            const float4 a  = *reinterpret_cast<const float4*>(&Qt[kk * 68 + r0]);
            const float4 b0 = *reinterpret_cast<const float4*>(&KPt[kk * 68 + c0]);
            const float4 b1 = *reinterpret_cast<const float4*>(&KPt[kk * 68 + c0 + 4]);
            const float ra[4] = {a.x, a.y, a.z, a.w};
            const float rb[8] = {b0.x, b0.y, b0.z, b0.w, b1.x, b1.y, b1.z, b1.w};
#pragma unroll
            for (int i = 0; i < 4; i++)
#pragma unroll
                for (int j = 0; j < 8; j++) s[i][j] += ra[i] * rb[j];
        }

        // Online softmax (row groups = 8 lanes sharing ty; xor-shuffle width 8)
#pragma unroll
        for (int i = 0; i < 4; i++) {
            float mx = s[i][0];
#pragma unroll
            for (int j = 1; j < 8; j++) mx = fmaxf(mx, s[i][j]);
#pragma unroll
            for (int off = 4; off > 0; off >>= 1)
                mx = fmaxf(mx, __shfl_xor_sync(0xffffffffu, mx, off, 8));

            const float mnew  = fmaxf(m_i[i], mx);
            const float alpha = __expf(m_i[i] - mnew);
            m_i[i] = mnew;

            float lsum = 0.0f;
#pragma unroll
            for (int j = 0; j < 8; j++) {
                const float p = __expf(s[i][j] - mnew);
                s[i][j] = p;
                lsum += p;
            }
#pragma unroll
            for (int off = 4; off > 0; off >>= 1)
                lsum += __shfl_xor_sync(0xffffffffu, lsum, off, 8);

            l_i[i] = l_i[i] * alpha + lsum;
#pragma unroll
            for (int j = 0; j < 8; j++) O[i][j] *= alpha;
        }

        __syncthreads();  // everyone done reading Kt
        // Store P transposed into Kt's buffer: Pt[k][qrow]
#pragma unroll
        for (int j = 0; j < 8; j++)
#pragma unroll
            for (int i = 0; i < 4; i++)
                KPt[(c0 + j) * 68 + (r0 + i)] = s[i][j];
        __syncthreads();

        // O += P V : micro 4x8 over 64 k
#pragma unroll 8
        for (int k = 0; k < 64; k++) {
            const float4 p  = *reinterpret_cast<const float4*>(&KPt[k * 68 + r0]);
            const float4 v0 = *reinterpret_cast<const float4*>(&Vs[k * 68 + c0]);
            const float4 v1 = *reinterpret_cast<const float4*>(&Vs[k * 68 + c0 + 4]);
            const float rp[4] = {p.x, p.y, p.z, p.w};
            const float rv[8] = {v0.x, v0.y, v0.z, v0.w, v1.x, v1.y, v1.z, v1.w};
#pragma unroll
            for (int i = 0; i < 4; i++)
#pragma unroll
                for (int j = 0; j < 8; j++) O[i][j] += rp[i] * rv[j];
        }
    }

    // Epilogue: normalize and store to g_o (contiguous (B,H,S,D))
    float* Op = g_o + (size_t)bh * PS * PD;
#pragma unroll
    for (int i = 0; i < 4; i++) {
        const float inv = 1.0f / l_i[i];
        float4 o0, o1;
        o0.x = O[i][0] * inv; o0.y = O[i][1] * inv;
        o0.z = O[i][2] * inv; o0.w = O[i][3] * inv;
        o1.x = O[i][4] * inv; o1.y = O[i][5] * inv;
        o1.z = O[i][6] * inv; o1.w = O[i][7] * inv;
        *reinterpret_cast<float4*>(&Op[(size_t)(q0 + r0 + i) * PD + c0])     = o0;
        *reinterpret_cast<float4*>(&Op[(size_t)(q0 + r0 + i) * PD + c0 + 4]) = o1;
    }
}

// ---------------------------------------------------------------------------
// kernel_launch
// ---------------------------------------------------------------------------
extern "C" void kernel_launch(void* const* d_in, const int* in_sizes, int n_in,
                              void* d_out, int out_size)
{
    const float* hidden = (const float*)d_in[0];
    const float* wq = (const float*)d_in[1];
    const float* wk = (const float*)d_in[2];
    const float* wv = (const float*)d_in[3];
    const float* wo = (const float*)d_in[4];
    const float* bo = (const float*)d_in[5];
    float* out = (float*)d_out;

    (void)in_sizes; (void)n_in; (void)out_size;

    cudaFuncSetAttribute(flash_attn, cudaFuncAttributeMaxDynamicSharedMemorySize,
                         ATT_SMEM_FLOATS * (int)sizeof(float));

    dim3 g_qkv(PE / BN, PM / BM, 3);       // (8, 64, 3)
    qkv_gemm<<<g_qkv, 256>>>(hidden, wq, wk, wv);

    dim3 g_att(PS / 64, PBH);              // (16, 128)
    flash_attn<<<g_att, 128, ATT_SMEM_FLOATS * (int)sizeof(float)>>>();

    dim3 g_out(PE / BN, PM / BM, 1);       // (8, 64)
    out_gemm<<<g_out, 256>>>(wo, bo, out);
}

// round 3
// speedup vs baseline: 1.5682x; 1.5682x over previous
#include <cuda_runtime.h>
#include <cstdint>
#include <cstddef>

// Problem constants
#define PB 8
#define PS 1024
#define PE 1024
#define PH 16
#define PD 64
#define PM (PB * PS)        // 8192 GEMM rows
#define PBH (PB * PH)       // 128 (b,h) pairs

// ---------------------------------------------------------------------------
// Scratch (static __device__, allocation-free per harness rules)
// ---------------------------------------------------------------------------
__device__ float g_q[PB * PS * PE];
__device__ float g_k[PB * PS * PE];
__device__ float g_v[PB * PS * PE];
__device__ float g_o[PB * PS * PE];     // attention output (B,H,S,D) contiguous

// ---------------------------------------------------------------------------
// Helpers
// ---------------------------------------------------------------------------
__device__ __forceinline__ float to_tf32(float x) {
    float y;
    asm("cvt.rna.tf32.f32 %0, %1;" : "=f"(y) : "f"(x));
    return y;
}

// warp-level tf32 MMA: D(16x8) += A(16x8) * B(8x8), fp32 accum.
// Supported on generic compute_103 target (sm_80+ PTX), unlike tcgen05.
__device__ __forceinline__ void mma_tf32(float c[4], const uint32_t a[4],
                                         const uint32_t b[2]) {
    asm volatile(
        "mma.sync.aligned.m16n8k8.row.col.f32.tf32.tf32.f32 "
        "{%0,%1,%2,%3}, {%4,%5,%6,%7}, {%8,%9}, {%0,%1,%2,%3};"
        : "+f"(c[0]), "+f"(c[1]), "+f"(c[2]), "+f"(c[3])
        : "r"(a[0]), "r"(a[1]), "r"(a[2]), "r"(a[3]), "r"(b[0]), "r"(b[1]));
}

// ---------------------------------------------------------------------------
// Tensor-core GEMM via mma.sync tf32:
//   C[M=8192, N=1024] = A[M, K=1024] * W[K, N]  (+ bias)
// Block tile 128x128, K-tile 32. 256 threads = 8 warps in a 2x4 grid,
// warp tile 64x32 (4 x 4 m16n8k8 fragments per k8).
// Smem: As[m][k] stride 36, Bs[k][n] stride 136 -> all fragment LDS.32 and
// staging STS.128 are bank-conflict-free.
// PERM=true: A is the (B,H,S,D)->(B,S,E) permuted view of g_o.
// ---------------------------------------------------------------------------
#define BM 128
#define BN 128
#define KT 32
#define ASTR 36
#define BSTR 136

template <bool PERM>
__device__ __forceinline__ void gemm_mma_body(const float* __restrict__ A,
                                              const float* __restrict__ W,
                                              const float* __restrict__ bias,
                                              float* __restrict__ C)
{
    __shared__ float As[BM * ASTR];   // 18432 B
    __shared__ float Bs[KT * BSTR];   // 17408 B

    const int tid  = threadIdx.x;     // 256
    const int lane = tid & 31;
    const int wid  = tid >> 5;
    const int m0 = blockIdx.y * BM;
    const int n0 = blockIdx.x * BN;
    const int wr0 = (wid & 1) * 64;   // warp row offset in tile
    const int wn0 = (wid >> 1) * 32;  // warp col offset in tile

    const int g  = lane >> 2;         // groupID 0..7
    const int t4 = lane & 3;          // threadID in group 0..3

    // Staging thread mapping
    const int a_m = tid >> 3;         // +i*32 : tile row
    const int a_q = (tid & 7) * 4;    // k offset (float4)
    const int b_k = tid >> 5;         // +i*8 : tile k row
    const int b_q = (tid & 31) * 4;   // n offset (float4)

    float c[4][4][4];
#pragma unroll
    for (int mi = 0; mi < 4; mi++)
#pragma unroll
        for (int nj = 0; nj < 4; nj++)
#pragma unroll
            for (int e = 0; e < 4; e++) c[mi][nj][e] = 0.0f;

    float4 sa[4], sb[4];

    // Prologue: stage tile kt=0
#pragma unroll
    for (int i = 0; i < 4; i++) {
        const int m = i * 32 + a_m;
        if (PERM) {
            const int gm = m0 + m;
            const int bb = gm >> 10, ss = gm & 1023;
            const int hh = a_q >> 6, dd = a_q & 63;
            sa[i] = *reinterpret_cast<const float4*>(
                &A[(((size_t)(bb * PH + hh)) * PS + ss) * PD + dd]);
        } else {
            sa[i] = *reinterpret_cast<const float4*>(
                &A[(size_t)(m0 + m) * PE + a_q]);
        }
        sb[i] = *reinterpret_cast<const float4*>(
            &W[(size_t)(i * 8 + b_k) * PE + n0 + b_q]);
    }

    for (int it = 0; it < PE / KT; it++) {
        __syncthreads();   // previous iteration's fragment reads done
        // Commit staged tile to smem with tf32 rounding
#pragma unroll
        for (int i = 0; i < 4; i++) {
            float4 v = sa[i];
            v.x = to_tf32(v.x); v.y = to_tf32(v.y);
            v.z = to_tf32(v.z); v.w = to_tf32(v.w);
            *reinterpret_cast<float4*>(&As[(i * 32 + a_m) * ASTR + a_q]) = v;
            float4 w = sb[i];
            w.x = to_tf32(w.x); w.y = to_tf32(w.y);
            w.z = to_tf32(w.z); w.w = to_tf32(w.w);
            *reinterpret_cast<float4*>(&Bs[(i * 8 + b_k) * BSTR + b_q]) = w;
        }
        __syncthreads();

        // Issue next tile's loads early (hidden behind the MMA loop)
        if (it + 1 < PE / KT) {
            const int kt = (it + 1) * KT;
#pragma unroll
            for (int i = 0; i < 4; i++) {
                const int m = i * 32 + a_m;
                const int gk = kt + a_q;
                if (PERM) {
                    const int gm = m0 + m;
                    const int bb = gm >> 10, ss = gm & 1023;
                    const int hh = gk >> 6, dd = gk & 63;
                    sa[i] = *reinterpret_cast<const float4*>(
                        &A[(((size_t)(bb * PH + hh)) * PS + ss) * PD + dd]);
                } else {
                    sa[i] = *reinterpret_cast<const float4*>(
                        &A[(size_t)(m0 + m) * PE + gk]);
                }
                sb[i] = *reinterpret_cast<const float4*>(
                    &W[(size_t)(kt + i * 8 + b_k) * PE + n0 + b_q]);
            }
        }

        // Compute: 4 k8 steps x 16 MMAs
#pragma unroll
        for (int k8 = 0; k8 < KT; k8 += 8) {
            uint32_t af[4][4];
#pragma unroll
            for (int mi = 0; mi < 4; mi++) {
                const int r = wr0 + mi * 16 + g;
                const int cc = k8 + t4;
                af[mi][0] = __float_as_uint(As[r * ASTR + cc]);
                af[mi][1] = __float_as_uint(As[(r + 8) * ASTR + cc]);
                af[mi][2] = __float_as_uint(As[r * ASTR + cc + 4]);
                af[mi][3] = __float_as_uint(As[(r + 8) * ASTR + cc + 4]);
            }
            uint32_t bf[4][2];
#pragma unroll
            for (int nj = 0; nj < 4; nj++) {
                const int nn = wn0 + nj * 8 + g;
                bf[nj][0] = __float_as_uint(Bs[(k8 + t4) * BSTR + nn]);
                bf[nj][1] = __float_as_uint(Bs[(k8 + t4 + 4) * BSTR + nn]);
            }
#pragma unroll
            for (int mi = 0; mi < 4; mi++)
#pragma unroll
                for (int nj = 0; nj < 4; nj++)
                    mma_tf32(c[mi][nj], af[mi], bf[nj]);
        }
    }

    // Epilogue: fragment -> gmem (st.v2 pairs), optional bias
#pragma unroll
    for (int mi = 0; mi < 4; mi++) {
        const int r0g = m0 + wr0 + mi * 16 + g;
#pragma unroll
        for (int nj = 0; nj < 4; nj++) {
            const int cg = n0 + wn0 + nj * 8 + 2 * t4;
            float b0 = 0.0f, b1 = 0.0f;
            if (bias) { b0 = bias[cg]; b1 = bias[cg + 1]; }
            float2 v0, v1;
            v0.x = c[mi][nj][0] + b0; v0.y = c[mi][nj][1] + b1;
            v1.x = c[mi][nj][2] + b0; v1.y = c[mi][nj][3] + b1;
            *reinterpret_cast<float2*>(&C[(size_t)r0g * PE + cg]) = v0;
            *reinterpret_cast<float2*>(&C[(size_t)(r0g + 8) * PE + cg]) = v1;
        }
    }
}

__global__ __launch_bounds__(256) void qkv_gemm_tc(const float* __restrict__ X,
                                                   const float* __restrict__ Wq,
                                                   const float* __restrict__ Wk,
                                                   const float* __restrict__ Wv)
{
    const float* W = (blockIdx.z == 0) ? Wq : (blockIdx.z == 1) ? Wk : Wv;
    float* C = (blockIdx.z == 0) ? g_q : (blockIdx.z == 1) ? g_k : g_v;
    gemm_mma_body<false>(X, W, nullptr, C);
}

__global__ __launch_bounds__(256) void out_gemm_tc(const float* __restrict__ Wo,
                                                   const float* __restrict__ bo,
                                                   float* __restrict__ out)
{
    gemm_mma_body<true>(g_o, Wo, bo, out);
}

// ---------------------------------------------------------------------------
// Flash attention fp32 (R1, unchanged). grid (16, 128), 128 threads.
// ---------------------------------------------------------------------------
#define ATT_SMEM_FLOATS (3 * 64 * 68)

__global__ __launch_bounds__(128) void flash_attn()
{
    extern __shared__ float sm[];
    float* Qt  = sm;                 // [64][68] Qt[d][qrow], pre-scaled
    float* KPt = sm + 64 * 68;       // [64][68] Kt[d][krow] then Pt[k][qrow]
    float* Vs  = sm + 2 * 64 * 68;   // [64][68] Vs[krow][d]

    const int tid = threadIdx.x;
    const int bh  = blockIdx.y;
    const int q0  = blockIdx.x * 64;

    const float* Q  = g_q + (size_t)bh * PS * PD;
    const float* Kg = g_k + (size_t)bh * PS * PD;
    const float* Vg = g_v + (size_t)bh * PS * PD;
    const float scale = 0.03125f;    // E^-0.5 (reference quirk)

    const int ty = tid >> 3;
    const int tx = tid & 7;
    const int r0 = ty * 4;
    const int c0 = tx * 8;

    for (int i = tid; i < 64 * 16; i += 128) {
        const int row = i >> 4;
        const int c4  = (i & 15) << 2;
        const float4 qv = *reinterpret_cast<const float4*>(&Q[(q0 + row) * PD + c4]);
        Qt[(c4 + 0) * 68 + row] = qv.x * scale;
        Qt[(c4 + 1) * 68 + row] = qv.y * scale;
        Qt[(c4 + 2) * 68 + row] = qv.z * scale;
        Qt[(c4 + 3) * 68 + row] = qv.w * scale;
    }

    float m_i[4], l_i[4], O[4][8];
#pragma unroll
    for (int i = 0; i < 4; i++) {
        m_i[i] = -1e30f; l_i[i] = 0.0f;
#pragma unroll
        for (int j = 0; j < 8; j++) O[i][j] = 0.0f;
    }

    for (int t = 0; t < 16; t++) {
        const int k0 = t * 64;
        __syncthreads();

        for (int i = tid; i < 64 * 16; i += 128) {
            const int row = i >> 4;
            const int c4  = (i & 15) << 2;
            const float4 kv = *reinterpret_cast<const float4*>(&Kg[(k0 + row) * PD + c4]);
            KPt[(c4 + 0) * 68 + row] = kv.x;
            KPt[(c4 + 1) * 68 + row] = kv.y;
            KPt[(c4 + 2) * 68 + row] = kv.z;
            KPt[(c4 + 3) * 68 + row] = kv.w;
            const float4 vv = *reinterpret_cast<const float4*>(&Vg[(k0 + row) * PD + c4]);
            *reinterpret_cast<float4*>(&Vs[row * 68 + c4]) = vv;
        }
        __syncthreads();

        float s[4][8];
#pragma unroll
        for (int i = 0; i < 4; i++)
#pragma unroll
            for (int j = 0; j < 8; j++) s[i][j] = 0.0f;

#pragma unroll 8
        for (int kk = 0; kk < 64; kk++) {
            const float4 a  = *reinterpret_cast<const float4*>(&Qt[kk * 68 + r0]);
            const float4 b0 = *reinterpret_cast<const float4*>(&KPt[kk * 68 + c0]);
            const float4 b1 = *reinterpret_cast<const float4*>(&KPt[kk * 68 + c0 + 4]);
            const float ra[4] = {a.x, a.y, a.z, a.w};
            const float rb[8] = {b0.x, b0.y, b0.z, b0.w, b1.x, b1.y, b1.z, b1.w};
#pragma unroll
            for (int i = 0; i < 4; i++)
#pragma unroll
                for (int j = 0; j < 8; j++) s[i][j] += ra[i] * rb[j];
        }

#pragma unroll
        for (int i = 0; i < 4; i++) {
            float mx = s[i][0];
#pragma unroll
            for (int j = 1; j < 8; j++) mx = fmaxf(mx, s[i][j]);
#pragma unroll
            for (int off = 4; off > 0; off >>= 1)
                mx = fmaxf(mx, __shfl_xor_sync(0xffffffffu, mx, off, 8));

            const float mnew  = fmaxf(m_i[i], mx);
            const float alpha = __expf(m_i[i] - mnew);
            m_i[i] = mnew;

            float lsum = 0.0f;
#pragma unroll
            for (int j = 0; j < 8; j++) {
                const float p = __expf(s[i][j] - mnew);
                s[i][j] = p;
                lsum += p;
            }
#pragma unroll
            for (int off = 4; off > 0; off >>= 1)
                lsum += __shfl_xor_sync(0xffffffffu, lsum, off, 8);

            l_i[i] = l_i[i] * alpha + lsum;
#pragma unroll
            for (int j = 0; j < 8; j++) O[i][j] *= alpha;
        }

        __syncthreads();
#pragma unroll
        for (int j = 0; j < 8; j++)
#pragma unroll
            for (int i = 0; i < 4; i++)
                KPt[(c0 + j) * 68 + (r0 + i)] = s[i][j];
        __syncthreads();

#pragma unroll 8
        for (int k = 0; k < 64; k++) {
            const float4 p  = *reinterpret_cast<const float4*>(&KPt[k * 68 + r0]);
            const float4 v0 = *reinterpret_cast<const float4*>(&Vs[k * 68 + c0]);
            const float4 v1 = *reinterpret_cast<const float4*>(&Vs[k * 68 + c0 + 4]);
            const float rp[4] = {p.x, p.y, p.z, p.w};
            const float rv[8] = {v0.x, v0.y, v0.z, v0.w, v1.x, v1.y, v1.z, v1.w};
#pragma unroll
            for (int i = 0; i < 4; i++)
#pragma unroll
                for (int j = 0; j < 8; j++) O[i][j] += rp[i] * rv[j];
        }
    }

    float* Op = g_o + (size_t)bh * PS * PD;
#pragma unroll
    for (int i = 0; i < 4; i++) {
        const float inv = 1.0f / l_i[i];
        float4 o0, o1;
        o0.x = O[i][0] * inv; o0.y = O[i][1] * inv;
        o0.z = O[i][2] * inv; o0.w = O[i][3] * inv;
        o1.x = O[i][4] * inv; o1.y = O[i][5] * inv;
        o1.z = O[i][6] * inv; o1.w = O[i][7] * inv;
        *reinterpret_cast<float4*>(&Op[(size_t)(q0 + r0 + i) * PD + c0])     = o0;
        *reinterpret_cast<float4*>(&Op[(size_t)(q0 + r0 + i) * PD + c0 + 4]) = o1;
    }
}

// ---------------------------------------------------------------------------
// kernel_launch
// ---------------------------------------------------------------------------
extern "C" void kernel_launch(void* const* d_in, const int* in_sizes, int n_in,
                              void* d_out, int out_size)
{
    const float* hidden = (const float*)d_in[0];
    const float* wq = (const float*)d_in[1];
    const float* wk = (const float*)d_in[2];
    const float* wv = (const float*)d_in[3];
    const float* wo = (const float*)d_in[4];
    const float* bo = (const float*)d_in[5];
    float* out = (float*)d_out;
    (void)in_sizes; (void)n_in; (void)out_size;

    cudaFuncSetAttribute(flash_attn, cudaFuncAttributeMaxDynamicSharedMemorySize,
                         ATT_SMEM_FLOATS * (int)sizeof(float));

    // QKV projections (mma.sync tf32)
    qkv_gemm_tc<<<dim3(PE / BN, PM / BM, 3), 256>>>(hidden, wq, wk, wv);

    // Attention (fp32 SIMT)
    flash_attn<<<dim3(PS / 64, PBH), 128, ATT_SMEM_FLOATS * (int)sizeof(float)>>>();

    // Output projection (mma.sync tf32) + bias
    out_gemm_tc<<<dim3(PE / BN, PM / BM, 1), 256>>>(wo, bo, out);
}

// round 4
// speedup vs baseline: 3.4197x; 2.1807x over previous
#include <cuda_runtime.h>
#include <cstdint>
#include <cstddef>

// Problem constants
#define PB 8
#define PS 1024
#define PE 1024
#define PH 16
#define PD 64
#define PM (PB * PS)        // 8192 GEMM rows
#define PBH (PB * PH)       // 128 (b,h) pairs

// ---------------------------------------------------------------------------
// Scratch (static __device__, allocation-free per harness rules)
// ---------------------------------------------------------------------------
__device__ float g_q[PB * PS * PE];
__device__ float g_k[PB * PS * PE];
__device__ float g_v[PB * PS * PE];
__device__ float g_o[PB * PS * PE];     // attention output (B,H,S,D) contiguous

// ---------------------------------------------------------------------------
// Helpers
// ---------------------------------------------------------------------------
__device__ __forceinline__ float to_tf32(float x) {
    float y;
    asm("cvt.rna.tf32.f32 %0, %1;" : "=f"(y) : "f"(x));
    return y;
}

// warp-level tf32 MMA: D(16x8) += A(16x8) * B(8x8), fp32 accum.
__device__ __forceinline__ void mma_tf32(float c[4], const uint32_t a[4],
                                         const uint32_t b[2]) {
    asm volatile(
        "mma.sync.aligned.m16n8k8.row.col.f32.tf32.tf32.f32 "
        "{%0,%1,%2,%3}, {%4,%5,%6,%7}, {%8,%9}, {%0,%1,%2,%3};"
        : "+f"(c[0]), "+f"(c[1]), "+f"(c[2]), "+f"(c[3])
        : "r"(a[0]), "r"(a[1]), "r"(a[2]), "r"(a[3]), "r"(b[0]), "r"(b[1]));
}

// ---------------------------------------------------------------------------
// Dense GEMM via mma.sync tf32 (unchanged from R3):
//   C[8192, 1024] = A * W (+bias); PERM=true reads A as permuted g_o.
// ---------------------------------------------------------------------------
#define BM 128
#define BN 128
#define KT 32
#define ASTR 36
#define BSTR 136

template <bool PERM>
__device__ __forceinline__ void gemm_mma_body(const float* __restrict__ A,
                                              const float* __restrict__ W,
                                              const float* __restrict__ bias,
                                              float* __restrict__ C)
{
    __shared__ float As[BM * ASTR];
    __shared__ float Bs[KT * BSTR];

    const int tid  = threadIdx.x;     // 256
    const int lane = tid & 31;
    const int wid  = tid >> 5;
    const int m0 = blockIdx.y * BM;
    const int n0 = blockIdx.x * BN;
    const int wr0 = (wid & 1) * 64;
    const int wn0 = (wid >> 1) * 32;

    const int g  = lane >> 2;
    const int t4 = lane & 3;

    const int a_m = tid >> 3;
    const int a_q = (tid & 7) * 4;
    const int b_k = tid >> 5;
    const int b_q = (tid & 31) * 4;

    float c[4][4][4];
#pragma unroll
    for (int mi = 0; mi < 4; mi++)
#pragma unroll
        for (int nj = 0; nj < 4; nj++)
#pragma unroll
            for (int e = 0; e < 4; e++) c[mi][nj][e] = 0.0f;

    float4 sa[4], sb[4];

#pragma unroll
    for (int i = 0; i < 4; i++) {
        const int m = i * 32 + a_m;
        if (PERM) {
            const int gm = m0 + m;
            const int bb = gm >> 10, ss = gm & 1023;
            const int hh = a_q >> 6, dd = a_q & 63;
            sa[i] = *reinterpret_cast<const float4*>(
                &A[(((size_t)(bb * PH + hh)) * PS + ss) * PD + dd]);
        } else {
            sa[i] = *reinterpret_cast<const float4*>(
                &A[(size_t)(m0 + m) * PE + a_q]);
        }
        sb[i] = *reinterpret_cast<const float4*>(
            &W[(size_t)(i * 8 + b_k) * PE + n0 + b_q]);
    }

    for (int it = 0; it < PE / KT; it++) {
        __syncthreads();
#pragma unroll
        for (int i = 0; i < 4; i++) {
            float4 v = sa[i];
            v.x = to_tf32(v.x); v.y = to_tf32(v.y);
            v.z = to_tf32(v.z); v.w = to_tf32(v.w);
            *reinterpret_cast<float4*>(&As[(i * 32 + a_m) * ASTR + a_q]) = v;
            float4 w = sb[i];
            w.x = to_tf32(w.x); w.y = to_tf32(w.y);
            w.z = to_tf32(w.z); w.w = to_tf32(w.w);
            *reinterpret_cast<float4*>(&Bs[(i * 8 + b_k) * BSTR + b_q]) = w;
        }
        __syncthreads();

        if (it + 1 < PE / KT) {
            const int kt = (it + 1) * KT;
#pragma unroll
            for (int i = 0; i < 4; i++) {
                const int m = i * 32 + a_m;
                const int gk = kt + a_q;
                if (PERM) {
                    const int gm = m0 + m;
                    const int bb = gm >> 10, ss = gm & 1023;
                    const int hh = gk >> 6, dd = gk & 63;
                    sa[i] = *reinterpret_cast<const float4*>(
                        &A[(((size_t)(bb * PH + hh)) * PS + ss) * PD + dd]);
                } else {
                    sa[i] = *reinterpret_cast<const float4*>(
                        &A[(size_t)(m0 + m) * PE + gk]);
                }
                sb[i] = *reinterpret_cast<const float4*>(
                    &W[(size_t)(kt + i * 8 + b_k) * PE + n0 + b_q]);
            }
        }

#pragma unroll
        for (int k8 = 0; k8 < KT; k8 += 8) {
            uint32_t af[4][4];
#pragma unroll
            for (int mi = 0; mi < 4; mi++) {
                const int r = wr0 + mi * 16 + g;
                const int cc = k8 + t4;
                af[mi][0] = __float_as_uint(As[r * ASTR + cc]);
                af[mi][1] = __float_as_uint(As[(r + 8) * ASTR + cc]);
                af[mi][2] = __float_as_uint(As[r * ASTR + cc + 4]);
                af[mi][3] = __float_as_uint(As[(r + 8) * ASTR + cc + 4]);
            }
            uint32_t bf[4][2];
#pragma unroll
            for (int nj = 0; nj < 4; nj++) {
                const int nn = wn0 + nj * 8 + g;
                bf[nj][0] = __float_as_uint(Bs[(k8 + t4) * BSTR + nn]);
                bf[nj][1] = __float_as_uint(Bs[(k8 + t4 + 4) * BSTR + nn]);
            }
#pragma unroll
            for (int mi = 0; mi < 4; mi++)
#pragma unroll
                for (int nj = 0; nj < 4; nj++)
                    mma_tf32(c[mi][nj], af[mi], bf[nj]);
        }
    }

#pragma unroll
    for (int mi = 0; mi < 4; mi++) {
        const int r0g = m0 + wr0 + mi * 16 + g;
#pragma unroll
        for (int nj = 0; nj < 4; nj++) {
            const int cg = n0 + wn0 + nj * 8 + 2 * t4;
            float b0 = 0.0f, b1 = 0.0f;
            if (bias) { b0 = bias[cg]; b1 = bias[cg + 1]; }
            float2 v0, v1;
            v0.x = c[mi][nj][0] + b0; v0.y = c[mi][nj][1] + b1;
            v1.x = c[mi][nj][2] + b0; v1.y = c[mi][nj][3] + b1;
            *reinterpret_cast<float2*>(&C[(size_t)r0g * PE + cg]) = v0;
            *reinterpret_cast<float2*>(&C[(size_t)(r0g + 8) * PE + cg]) = v1;
        }
    }
}

__global__ __launch_bounds__(256) void qkv_gemm_tc(const float* __restrict__ X,
                                                   const float* __restrict__ Wq,
                                                   const float* __restrict__ Wk,
                                                   const float* __restrict__ Wv)
{
    const float* W = (blockIdx.z == 0) ? Wq : (blockIdx.z == 1) ? Wk : Wv;
    float* C = (blockIdx.z == 0) ? g_q : (blockIdx.z == 1) ? g_k : g_v;
    gemm_mma_body<false>(X, W, nullptr, C);
}

__global__ __launch_bounds__(256) void out_gemm_tc(const float* __restrict__ Wo,
                                                   const float* __restrict__ bo,
                                                   float* __restrict__ out)
{
    gemm_mma_body<true>(g_o, Wo, bo, out);
}

// ---------------------------------------------------------------------------
// Flash attention via mma.sync tf32.
// Br=128 (block), Bc=64 (k-tile). 256 threads = 8 warps, each warp owns 16 q
// rows. grid (S/128=8, BH=128).
//   S = Q Kt : A = Qs[q][d] row-major, B = Ks[kc][d] ("col" = [n][k]) -> natural.
//   O += P V : A = Ps[q][kc] row-major, B = Vs[kc][d] read column-wise.
// Strides: Qs/Ks/Ps 68 (frag banks 4g+t4 distinct), Vs 72 (banks 8t4+g distinct).
// P goes through per-warp-private smem rows (only __syncwarp between write/read).
// Smem: (128*68 + 64*68 + 64*72 + 128*68) * 4 = 105472 B.
// ---------------------------------------------------------------------------
#define QSTR 68
#define KSTR 68
#define VSTR 72
#define PSTR 68
#define ATT_SMEM_BYTES ((128 * QSTR + 64 * KSTR + 64 * VSTR + 128 * PSTR) * 4)

__global__ __launch_bounds__(256) void flash_attn_tc()
{
    extern __shared__ float sm[];
    float* Qs = sm;                              // [128][QSTR]
    float* Ks = Qs + 128 * QSTR;                 // [64][KSTR]
    float* Vs = Ks + 64 * KSTR;                  // [64][VSTR]
    float* Ps = Vs + 64 * VSTR;                  // [128][PSTR]

    const int tid  = threadIdx.x;    // 256
    const int lane = tid & 31;
    const int wid  = tid >> 5;       // 0..7 -> q rows wid*16..+15
    const int g    = lane >> 2;      // 0..7
    const int t4   = lane & 3;       // 0..3
    const int bh   = blockIdx.y;
    const int q0   = blockIdx.x * 128;

    const float* Qg = g_q + (size_t)bh * PS * PD;
    const float* Kg = g_k + (size_t)bh * PS * PD;
    const float* Vg = g_v + (size_t)bh * PS * PD;
    const float scale = 0.03125f;    // E^-0.5 (reference quirk)

    // Stage Q tile: 128x64, pre-scaled + tf32. 2048 float4 / 256 thr = 8 each.
#pragma unroll
    for (int i = 0; i < 8; i++) {
        const int idx = i * 256 + tid;
        const int row = idx >> 4;
        const int c4  = (idx & 15) << 2;
        float4 v = *reinterpret_cast<const float4*>(&Qg[(size_t)(q0 + row) * PD + c4]);
        v.x = to_tf32(v.x * scale); v.y = to_tf32(v.y * scale);
        v.z = to_tf32(v.z * scale); v.w = to_tf32(v.w * scale);
        *reinterpret_cast<float4*>(&Qs[row * QSTR + c4]) = v;
    }

    float m_i[2] = {-1e30f, -1e30f};
    float l_i[2] = {0.0f, 0.0f};
    float o[8][4];
#pragma unroll
    for (int nj = 0; nj < 8; nj++)
#pragma unroll
        for (int e = 0; e < 4; e++) o[nj][e] = 0.0f;

    const int wr = wid * 16;         // warp's q-row base in tile

    for (int t = 0; t < 16; t++) {
        const int k0 = t * 64;
        __syncthreads();             // prior tile's K/V reads complete

        // Stage K (tf32) and V (tf32): 64x64 each, 1024 float4 / 256 thr = 4.
#pragma unroll
        for (int i = 0; i < 4; i++) {
            const int idx = i * 256 + tid;
            const int row = idx >> 4;
            const int c4  = (idx & 15) << 2;
            float4 kv = *reinterpret_cast<const float4*>(&Kg[(size_t)(k0 + row) * PD + c4]);
            kv.x = to_tf32(kv.x); kv.y = to_tf32(kv.y);
            kv.z = to_tf32(kv.z); kv.w = to_tf32(kv.w);
            *reinterpret_cast<float4*>(&Ks[row * KSTR + c4]) = kv;
            float4 vv = *reinterpret_cast<const float4*>(&Vg[(size_t)(k0 + row) * PD + c4]);
            vv.x = to_tf32(vv.x); vv.y = to_tf32(vv.y);
            vv.z = to_tf32(vv.z); vv.w = to_tf32(vv.w);
            *reinterpret_cast<float4*>(&Vs[row * VSTR + c4]) = vv;
        }
        __syncthreads();

        // ---- S = Q Kt : 16x64 per warp, 8 k8 steps x 8 n-frags ----
        float s[8][4];
#pragma unroll
        for (int nj = 0; nj < 8; nj++)
#pragma unroll
            for (int e = 0; e < 4; e++) s[nj][e] = 0.0f;

#pragma unroll
        for (int k8 = 0; k8 < 64; k8 += 8) {
            uint32_t af[4];
            af[0] = __float_as_uint(Qs[(wr + g) * QSTR + k8 + t4]);
            af[1] = __float_as_uint(Qs[(wr + g + 8) * QSTR + k8 + t4]);
            af[2] = __float_as_uint(Qs[(wr + g) * QSTR + k8 + t4 + 4]);
            af[3] = __float_as_uint(Qs[(wr + g + 8) * QSTR + k8 + t4 + 4]);
#pragma unroll
            for (int nj = 0; nj < 8; nj++) {
                uint32_t bf[2];
                bf[0] = __float_as_uint(Ks[(nj * 8 + g) * KSTR + k8 + t4]);
                bf[1] = __float_as_uint(Ks[(nj * 8 + g) * KSTR + k8 + t4 + 4]);
                mma_tf32(s[nj], af, bf);
            }
        }

        // ---- online softmax (rows g and g+8; quad = lanes sharing g) ----
        float mx0 = s[0][0], mx1 = s[0][2];
#pragma unroll
        for (int nj = 0; nj < 8; nj++) {
            mx0 = fmaxf(mx0, fmaxf(s[nj][0], s[nj][1]));
            mx1 = fmaxf(mx1, fmaxf(s[nj][2], s[nj][3]));
        }
#pragma unroll
        for (int off = 1; off <= 2; off <<= 1) {
            mx0 = fmaxf(mx0, __shfl_xor_sync(0xffffffffu, mx0, off));
            mx1 = fmaxf(mx1, __shfl_xor_sync(0xffffffffu, mx1, off));
        }

        const float mn0 = fmaxf(m_i[0], mx0);
        const float mn1 = fmaxf(m_i[1], mx1);
        const float al0 = __expf(m_i[0] - mn0);
        const float al1 = __expf(m_i[1] - mn1);
        m_i[0] = mn0; m_i[1] = mn1;

        float ls0 = 0.0f, ls1 = 0.0f;
#pragma unroll
        for (int nj = 0; nj < 8; nj++) {
            s[nj][0] = __expf(s[nj][0] - mn0);
            s[nj][1] = __expf(s[nj][1] - mn0);
            s[nj][2] = __expf(s[nj][2] - mn1);
            s[nj][3] = __expf(s[nj][3] - mn1);
            ls0 += s[nj][0] + s[nj][1];
            ls1 += s[nj][2] + s[nj][3];
        }
#pragma unroll
        for (int off = 1; off <= 2; off <<= 1) {
            ls0 += __shfl_xor_sync(0xffffffffu, ls0, off);
            ls1 += __shfl_xor_sync(0xffffffffu, ls1, off);
        }
        l_i[0] = l_i[0] * al0 + ls0;
        l_i[1] = l_i[1] * al1 + ls1;

#pragma unroll
        for (int nj = 0; nj < 8; nj++) {
            o[nj][0] *= al0; o[nj][1] *= al0;
            o[nj][2] *= al1; o[nj][3] *= al1;
        }

        // ---- P -> warp-private smem rows (tf32 for the PV mma) ----
#pragma unroll
        for (int nj = 0; nj < 8; nj++) {
            float2 p0, p1;
            p0.x = to_tf32(s[nj][0]); p0.y = to_tf32(s[nj][1]);
            p1.x = to_tf32(s[nj][2]); p1.y = to_tf32(s[nj][3]);
            *reinterpret_cast<float2*>(&Ps[(wr + g) * PSTR + nj * 8 + 2 * t4]) = p0;
            *reinterpret_cast<float2*>(&Ps[(wr + g + 8) * PSTR + nj * 8 + 2 * t4]) = p1;
        }
        __syncwarp();

        // ---- O += P V : 8 k8 steps x 8 d-frags ----
#pragma unroll
        for (int k8 = 0; k8 < 64; k8 += 8) {
            uint32_t af[4];
            af[0] = __float_as_uint(Ps[(wr + g) * PSTR + k8 + t4]);
            af[1] = __float_as_uint(Ps[(wr + g + 8) * PSTR + k8 + t4]);
            af[2] = __float_as_uint(Ps[(wr + g) * PSTR + k8 + t4 + 4]);
            af[3] = __float_as_uint(Ps[(wr + g + 8) * PSTR + k8 + t4 + 4]);
#pragma unroll
            for (int nj = 0; nj < 8; nj++) {
                uint32_t bf[2];
                bf[0] = __float_as_uint(Vs[(k8 + t4) * VSTR + nj * 8 + g]);
                bf[1] = __float_as_uint(Vs[(k8 + t4 + 4) * VSTR + nj * 8 + g]);
                mma_tf32(o[nj], af, bf);
            }
        }
        __syncwarp();   // Ps reads done before next tile's softmax overwrites
    }

    // ---- epilogue: normalize, store to g_o (B,H,S,D) ----
    const float inv0 = 1.0f / l_i[0];
    const float inv1 = 1.0f / l_i[1];
    float* Op = g_o + (size_t)bh * PS * PD;
#pragma unroll
    for (int nj = 0; nj < 8; nj++) {
        const int cg = nj * 8 + 2 * t4;
        float2 v0, v1;
        v0.x = o[nj][0] * inv0; v0.y = o[nj][1] * inv0;
        v1.x = o[nj][2] * inv1; v1.y = o[nj][3] * inv1;
        *reinterpret_cast<float2*>(&Op[(size_t)(q0 + wr + g) * PD + cg]) = v0;
        *reinterpret_cast<float2*>(&Op[(size_t)(q0 + wr + g + 8) * PD + cg]) = v1;
    }
}

// ---------------------------------------------------------------------------
// kernel_launch
// ---------------------------------------------------------------------------
extern "C" void kernel_launch(void* const* d_in, const int* in_sizes, int n_in,
                              void* d_out, int out_size)
{
    const float* hidden = (const float*)d_in[0];
    const float* wq = (const float*)d_in[1];
    const float* wk = (const float*)d_in[2];
    const float* wv = (const float*)d_in[3];
    const float* wo = (const float*)d_in[4];
    const float* bo = (const float*)d_in[5];
    float* out = (float*)d_out;
    (void)in_sizes; (void)n_in; (void)out_size;

    cudaFuncSetAttribute(flash_attn_tc, cudaFuncAttributeMaxDynamicSharedMemorySize,
                         ATT_SMEM_BYTES);

    // QKV projections (mma.sync tf32)
    qkv_gemm_tc<<<dim3(PE / BN, PM / BM, 3), 256>>>(hidden, wq, wk, wv);

    // Attention (mma.sync tf32 flash)
    flash_attn_tc<<<dim3(PS / 128, PBH), 256, ATT_SMEM_BYTES>>>();

    // Output projection (mma.sync tf32) + bias
    out_gemm_tc<<<dim3(PE / BN, PM / BM, 1), 256>>>(wo, bo, out);
}

// round 5
// speedup vs baseline: 3.5659x; 1.0427x over previous
#include <cuda_runtime.h>
#include <cstdint>
#include <cstddef>

// Problem constants
#define PB 8
#define PS 1024
#define PE 1024
#define PH 16
#define PD 64
#define PM (PB * PS)        // 8192 GEMM rows
#define PBH (PB * PH)       // 128 (b,h) pairs

// ---------------------------------------------------------------------------
// Scratch (static __device__, allocation-free per harness rules)
// ---------------------------------------------------------------------------
__device__ float g_q[PB * PS * PE];
__device__ float g_k[PB * PS * PE];
__device__ float g_v[PB * PS * PE];
__device__ float g_o[PB * PS * PE];     // attention output (B,H,S,D) contiguous

// ---------------------------------------------------------------------------
// Helpers
// ---------------------------------------------------------------------------
__device__ __forceinline__ float to_tf32(float x) {
    float y;
    asm("cvt.rna.tf32.f32 %0, %1;" : "=f"(y) : "f"(x));
    return y;
}

// warp-level tf32 MMA: D(16x8) += A(16x8) * B(8x8), fp32 accum.
__device__ __forceinline__ void mma_tf32(float c[4], const uint32_t a[4],
                                         const uint32_t b[2]) {
    asm volatile(
        "mma.sync.aligned.m16n8k8.row.col.f32.tf32.tf32.f32 "
        "{%0,%1,%2,%3}, {%4,%5,%6,%7}, {%8,%9}, {%0,%1,%2,%3};"
        : "+f"(c[0]), "+f"(c[1]), "+f"(c[2]), "+f"(c[3])
        : "r"(a[0]), "r"(a[1]), "r"(a[2]), "r"(a[3]), "r"(b[0]), "r"(b[1]));
}

// ---------------------------------------------------------------------------
// Dense GEMM via mma.sync tf32, double-buffered smem:
//   C[8192, 1024] = A * W (+bias); PERM=true reads A as permuted g_o.
// Block tile 128x256, K-tile 32. 8 warps in 2(m) x 4(n), warp tile 64x64
// (4 x 8 m16n8k8 fragments per k8). One __syncthreads per K-iteration.
// As[m][k] stride 36 (frag banks 4g+t4 distinct, STS.128 phases conflict-free),
// Bs[k][n] stride 264 (264%32==8 -> frag banks 8*t4+g distinct).
// Smem: 2*(128*36 + 32*264)*4 = 104448 B (dynamic).
// ---------------------------------------------------------------------------
#define BM 128
#define BN 256
#define KT 32
#define ASTR 36
#define BSTR 264
#define ASZ (BM * ASTR)          // 4608 floats
#define BSZ (KT * BSTR)          // 8448 floats
#define GEMM_SMEM_BYTES (2 * (ASZ + BSZ) * 4)

template <bool PERM>
__device__ __forceinline__ void gemm_mma_body(const float* __restrict__ A,
                                              const float* __restrict__ W,
                                              const float* __restrict__ bias,
                                              float* __restrict__ C)
{
    extern __shared__ float smg[];
    float* Asb = smg;                    // [2][ASZ]
    float* Bsb = smg + 2 * ASZ;          // [2][BSZ]

    const int tid  = threadIdx.x;        // 256
    const int lane = tid & 31;
    const int wid  = tid >> 5;
    const int m0 = blockIdx.y * BM;
    const int n0 = blockIdx.x * BN;
    const int wr0 = (wid & 1) * 64;      // warp m offset
    const int wn0 = (wid >> 1) * 64;     // warp n offset

    const int g  = lane >> 2;
    const int t4 = lane & 3;

    // Staging mappings
    const int a_r = tid >> 3;            // +i*32 : A tile row (0..127)
    const int a_q = (tid & 7) * 4;       // A k offset (float4)
    const int b_r = tid >> 6;            // +i*4 : B tile k row (0..31)
    const int b_q = (tid & 63) * 4;      // B n offset (float4)

    float c[4][8][4];
#pragma unroll
    for (int mi = 0; mi < 4; mi++)
#pragma unroll
        for (int nj = 0; nj < 8; nj++)
#pragma unroll
            for (int e = 0; e < 4; e++) c[mi][nj][e] = 0.0f;

    float4 sa[4], sb[8];

    // Prologue: prefetch tile kt=0
#pragma unroll
    for (int i = 0; i < 4; i++) {
        const int m = i * 32 + a_r;
        if (PERM) {
            const int gm = m0 + m;
            const int bb = gm >> 10, ss = gm & 1023;
            const int hh = a_q >> 6, dd = a_q & 63;
            sa[i] = *reinterpret_cast<const float4*>(
                &A[(((size_t)(bb * PH + hh)) * PS + ss) * PD + dd]);
        } else {
            sa[i] = *reinterpret_cast<const float4*>(
                &A[(size_t)(m0 + m) * PE + a_q]);
        }
    }
#pragma unroll
    for (int i = 0; i < 8; i++)
        sb[i] = *reinterpret_cast<const float4*>(
            &W[(size_t)(i * 4 + b_r) * PE + n0 + b_q]);

    for (int it = 0; it < PE / KT; it++) {
        float* As = Asb + (it & 1) * ASZ;
        float* Bs = Bsb + (it & 1) * BSZ;

        // Commit staged tile (tf32 rounding at staging)
#pragma unroll
        for (int i = 0; i < 4; i++) {
            float4 v = sa[i];
            v.x = to_tf32(v.x); v.y = to_tf32(v.y);
            v.z = to_tf32(v.z); v.w = to_tf32(v.w);
            *reinterpret_cast<float4*>(&As[(i * 32 + a_r) * ASTR + a_q]) = v;
        }
#pragma unroll
        for (int i = 0; i < 8; i++) {
            float4 w = sb[i];
            w.x = to_tf32(w.x); w.y = to_tf32(w.y);
            w.z = to_tf32(w.z); w.w = to_tf32(w.w);
            *reinterpret_cast<float4*>(&Bs[(i * 4 + b_r) * BSTR + b_q]) = w;
        }
        __syncthreads();   // single barrier per iteration (double buffer)

        // Prefetch next tile (overlaps the MMA loop below)
        if (it + 1 < PE / KT) {
            const int kt = (it + 1) * KT;
#pragma unroll
            for (int i = 0; i < 4; i++) {
                const int m = i * 32 + a_r;
                const int gk = kt + a_q;
                if (PERM) {
                    const int gm = m0 + m;
                    const int bb = gm >> 10, ss = gm & 1023;
                    const int hh = gk >> 6, dd = gk & 63;
                    sa[i] = *reinterpret_cast<const float4*>(
                        &A[(((size_t)(bb * PH + hh)) * PS + ss) * PD + dd]);
                } else {
                    sa[i] = *reinterpret_cast<const float4*>(
                        &A[(size_t)(m0 + m) * PE + gk]);
                }
            }
#pragma unroll
            for (int i = 0; i < 8; i++)
                sb[i] = *reinterpret_cast<const float4*>(
                    &W[(size_t)(kt + i * 4 + b_r) * PE + n0 + b_q]);
        }

        // Compute: 4 k8 steps x 32 MMAs (warp tile 64x64)
#pragma unroll
        for (int k8 = 0; k8 < KT; k8 += 8) {
            uint32_t af[4][4];
#pragma unroll
            for (int mi = 0; mi < 4; mi++) {
                const int r = wr0 + mi * 16 + g;
                const int cc = k8 + t4;
                af[mi][0] = __float_as_uint(As[r * ASTR + cc]);
                af[mi][1] = __float_as_uint(As[(r + 8) * ASTR + cc]);
                af[mi][2] = __float_as_uint(As[r * ASTR + cc + 4]);
                af[mi][3] = __float_as_uint(As[(r + 8) * ASTR + cc + 4]);
            }
            uint32_t bf[8][2];
#pragma unroll
            for (int nj = 0; nj < 8; nj++) {
                const int nn = wn0 + nj * 8 + g;
                bf[nj][0] = __float_as_uint(Bs[(k8 + t4) * BSTR + nn]);
                bf[nj][1] = __float_as_uint(Bs[(k8 + t4 + 4) * BSTR + nn]);
            }
#pragma unroll
            for (int mi = 0; mi < 4; mi++)
#pragma unroll
                for (int nj = 0; nj < 8; nj++)
                    mma_tf32(c[mi][nj], af[mi], bf[nj]);
        }
        __syncthreads();   // all reads of this buffer done before it is refilled
    }

    // Epilogue
#pragma unroll
    for (int mi = 0; mi < 4; mi++) {
        const int r0g = m0 + wr0 + mi * 16 + g;
#pragma unroll
        for (int nj = 0; nj < 8; nj++) {
            const int cg = n0 + wn0 + nj * 8 + 2 * t4;
            float b0 = 0.0f, b1 = 0.0f;
            if (bias) { b0 = bias[cg]; b1 = bias[cg + 1]; }
            float2 v0, v1;
            v0.x = c[mi][nj][0] + b0; v0.y = c[mi][nj][1] + b1;
            v1.x = c[mi][nj][2] + b0; v1.y = c[mi][nj][3] + b1;
            *reinterpret_cast<float2*>(&C[(size_t)r0g * PE + cg]) = v0;
            *reinterpret_cast<float2*>(&C[(size_t)(r0g + 8) * PE + cg]) = v1;
        }
    }
}

__global__ __launch_bounds__(256) void qkv_gemm_tc(const float* __restrict__ X,
                                                   const float* __restrict__ Wq,
                                                   const float* __restrict__ Wk,
                                                   const float* __restrict__ Wv)
{
    const float* W = (blockIdx.z == 0) ? Wq : (blockIdx.z == 1) ? Wk : Wv;
    float* C = (blockIdx.z == 0) ? g_q : (blockIdx.z == 1) ? g_k : g_v;
    gemm_mma_body<false>(X, W, nullptr, C);
}

__global__ __launch_bounds__(256) void out_gemm_tc(const float* __restrict__ Wo,
                                                   const float* __restrict__ bo,
                                                   float* __restrict__ out)
{
    gemm_mma_body<true>(g_o, Wo, bo, out);
}

// ---------------------------------------------------------------------------
// Flash attention via mma.sync tf32, K/V double-buffered.
// Br=128, Bc=64, 256 threads = 8 warps x 16 q rows. grid (8, 128).
// Smem: Qs[128][68] + 2x(Ks[64][68] + Vs[64][72]) + Ps[128][68] = 141312 B.
// ---------------------------------------------------------------------------
#define QSTR 68
#define KSTR 68
#define VSTR 72
#define PSTR 68
#define KSZ (64 * KSTR)
#define VSZ (64 * VSTR)
#define ATT_SMEM_BYTES ((128 * QSTR + 2 * (KSZ + VSZ) + 128 * PSTR) * 4)

__global__ __launch_bounds__(256) void flash_attn_tc()
{
    extern __shared__ float sm[];
    float* Qs  = sm;                         // [128][QSTR]
    float* Ksb = Qs + 128 * QSTR;            // [2][KSZ]
    float* Vsb = Ksb + 2 * KSZ;              // [2][VSZ]
    float* Ps  = Vsb + 2 * VSZ;              // [128][PSTR]

    const int tid  = threadIdx.x;    // 256
    const int lane = tid & 31;
    const int wid  = tid >> 5;
    const int g    = lane >> 2;
    const int t4   = lane & 3;
    const int bh   = blockIdx.y;
    const int q0   = blockIdx.x * 128;

    const float* Qg = g_q + (size_t)bh * PS * PD;
    const float* Kg = g_k + (size_t)bh * PS * PD;
    const float* Vg = g_v + (size_t)bh * PS * PD;
    const float scale = 0.03125f;    // E^-0.5 (reference quirk)

    // Stage Q tile: 128x64, pre-scaled + tf32
#pragma unroll
    for (int i = 0; i < 8; i++) {
        const int idx = i * 256 + tid;
        const int row = idx >> 4;
        const int c4  = (idx & 15) << 2;
        float4 v = *reinterpret_cast<const float4*>(&Qg[(size_t)(q0 + row) * PD + c4]);
        v.x = to_tf32(v.x * scale); v.y = to_tf32(v.y * scale);
        v.z = to_tf32(v.z * scale); v.w = to_tf32(v.w * scale);
        *reinterpret_cast<float4*>(&Qs[row * QSTR + c4]) = v;
    }

    float m_i[2] = {-1e30f, -1e30f};
    float l_i[2] = {0.0f, 0.0f};
    float o[8][4];
#pragma unroll
    for (int nj = 0; nj < 8; nj++)
#pragma unroll
        for (int e = 0; e < 4; e++) o[nj][e] = 0.0f;

    const int wr = wid * 16;

    // Prefetch K/V tile 0
    float4 ka[4], va[4];
#pragma unroll
    for (int i = 0; i < 4; i++) {
        const int idx = i * 256 + tid;
        const int row = idx >> 4;
        const int c4  = (idx & 15) << 2;
        ka[i] = *reinterpret_cast<const float4*>(&Kg[(size_t)row * PD + c4]);
        va[i] = *reinterpret_cast<const float4*>(&Vg[(size_t)row * PD + c4]);
    }

    for (int t = 0; t < 16; t++) {
        float* Ks = Ksb + (t & 1) * KSZ;
        float* Vs = Vsb + (t & 1) * VSZ;

        // Commit staged K/V (tf32)
#pragma unroll
        for (int i = 0; i < 4; i++) {
            const int idx = i * 256 + tid;
            const int row = idx >> 4;
            const int c4  = (idx & 15) << 2;
            float4 kv = ka[i];
            kv.x = to_tf32(kv.x); kv.y = to_tf32(kv.y);
            kv.z = to_tf32(kv.z); kv.w = to_tf32(kv.w);
            *reinterpret_cast<float4*>(&Ks[row * KSTR + c4]) = kv;
            float4 vv = va[i];
            vv.x = to_tf32(vv.x); vv.y = to_tf32(vv.y);
            vv.z = to_tf32(vv.z); vv.w = to_tf32(vv.w);
            *reinterpret_cast<float4*>(&Vs[row * VSTR + c4]) = vv;
        }
        __syncthreads();   // also covers initial Qs staging at t=0

        // Prefetch next K/V tile (overlaps compute)
        if (t + 1 < 16) {
            const int k0n = (t + 1) * 64;
#pragma unroll
            for (int i = 0; i < 4; i++) {
                const int idx = i * 256 + tid;
                const int row = idx >> 4;
                const int c4  = (idx & 15) << 2;
                ka[i] = *reinterpret_cast<const float4*>(&Kg[(size_t)(k0n + row) * PD + c4]);
                va[i] = *reinterpret_cast<const float4*>(&Vg[(size_t)(k0n + row) * PD + c4]);
            }
        }

        // ---- S = Q Kt : 16x64 per warp ----
        float s[8][4];
#pragma unroll
        for (int nj = 0; nj < 8; nj++)
#pragma unroll
            for (int e = 0; e < 4; e++) s[nj][e] = 0.0f;

#pragma unroll
        for (int k8 = 0; k8 < 64; k8 += 8) {
            uint32_t af[4];
            af[0] = __float_as_uint(Qs[(wr + g) * QSTR + k8 + t4]);
            af[1] = __float_as_uint(Qs[(wr + g + 8) * QSTR + k8 + t4]);
            af[2] = __float_as_uint(Qs[(wr + g) * QSTR + k8 + t4 + 4]);
            af[3] = __float_as_uint(Qs[(wr + g + 8) * QSTR + k8 + t4 + 4]);
#pragma unroll
            for (int nj = 0; nj < 8; nj++) {
                uint32_t bf[2];
                bf[0] = __float_as_uint(Ks[(nj * 8 + g) * KSTR + k8 + t4]);
                bf[1] = __float_as_uint(Ks[(nj * 8 + g) * KSTR + k8 + t4 + 4]);
                mma_tf32(s[nj], af, bf);
            }
        }

        // ---- online softmax ----
        float mx0 = s[0][0], mx1 = s[0][2];
#pragma unroll
        for (int nj = 0; nj < 8; nj++) {
            mx0 = fmaxf(mx0, fmaxf(s[nj][0], s[nj][1]));
            mx1 = fmaxf(mx1, fmaxf(s[nj][2], s[nj][3]));
        }
#pragma unroll
        for (int off = 1; off <= 2; off <<= 1) {
            mx0 = fmaxf(mx0, __shfl_xor_sync(0xffffffffu, mx0, off));
            mx1 = fmaxf(mx1, __shfl_xor_sync(0xffffffffu, mx1, off));
        }

        const float mn0 = fmaxf(m_i[0], mx0);
        const float mn1 = fmaxf(m_i[1], mx1);
        const float al0 = __expf(m_i[0] - mn0);
        const float al1 = __expf(m_i[1] - mn1);
        m_i[0] = mn0; m_i[1] = mn1;

        float ls0 = 0.0f, ls1 = 0.0f;
#pragma unroll
        for (int nj = 0; nj < 8; nj++) {
            s[nj][0] = __expf(s[nj][0] - mn0);
            s[nj][1] = __expf(s[nj][1] - mn0);
            s[nj][2] = __expf(s[nj][2] - mn1);
            s[nj][3] = __expf(s[nj][3] - mn1);
            ls0 += s[nj][0] + s[nj][1];
            ls1 += s[nj][2] + s[nj][3];
        }
#pragma unroll
        for (int off = 1; off <= 2; off <<= 1) {
            ls0 += __shfl_xor_sync(0xffffffffu, ls0, off);
            ls1 += __shfl_xor_sync(0xffffffffu, ls1, off);
        }
        l_i[0] = l_i[0] * al0 + ls0;
        l_i[1] = l_i[1] * al1 + ls1;

#pragma unroll
        for (int nj = 0; nj < 8; nj++) {
            o[nj][0] *= al0; o[nj][1] *= al0;
            o[nj][2] *= al1; o[nj][3] *= al1;
        }

        // ---- P -> warp-private smem rows (tf32) ----
#pragma unroll
        for (int nj = 0; nj < 8; nj++) {
            float2 p0, p1;
            p0.x = to_tf32(s[nj][0]); p0.y = to_tf32(s[nj][1]);
            p1.x = to_tf32(s[nj][2]); p1.y = to_tf32(s[nj][3]);
            *reinterpret_cast<float2*>(&Ps[(wr + g) * PSTR + nj * 8 + 2 * t4]) = p0;
            *reinterpret_cast<float2*>(&Ps[(wr + g + 8) * PSTR + nj * 8 + 2 * t4]) = p1;
        }
        __syncwarp();

        // ---- O += P V ----
#pragma unroll
        for (int k8 = 0; k8 < 64; k8 += 8) {
            uint32_t af[4];
            af[0] = __float_as_uint(Ps[(wr + g) * PSTR + k8 + t4]);
            af[1] = __float_as_uint(Ps[(wr + g + 8) * PSTR + k8 + t4]);
            af[2] = __float_as_uint(Ps[(wr + g) * PSTR + k8 + t4 + 4]);
            af[3] = __float_as_uint(Ps[(wr + g + 8) * PSTR + k8 + t4 + 4]);
#pragma unroll
            for (int nj = 0; nj < 8; nj++) {
                uint32_t bf[2];
                bf[0] = __float_as_uint(Vs[(k8 + t4) * VSTR + nj * 8 + g]);
                bf[1] = __float_as_uint(Vs[(k8 + t4 + 4) * VSTR + nj * 8 + g]);
                mma_tf32(o[nj], af, bf);
            }
        }
        __syncthreads();   // K/V buffer reads done before refill (2 tiles ahead)
    }

    // ---- epilogue ----
    const float inv0 = 1.0f / l_i[0];
    const float inv1 = 1.0f / l_i[1];
    float* Op = g_o + (size_t)bh * PS * PD;
#pragma unroll
    for (int nj = 0; nj < 8; nj++) {
        const int cg = nj * 8 + 2 * t4;
        float2 v0, v1;
        v0.x = o[nj][0] * inv0; v0.y = o[nj][1] * inv0;
        v1.x = o[nj][2] * inv1; v1.y = o[nj][3] * inv1;
        *reinterpret_cast<float2*>(&Op[(size_t)(q0 + wr + g) * PD + cg]) = v0;
        *reinterpret_cast<float2*>(&Op[(size_t)(q0 + wr + g + 8) * PD + cg]) = v1;
    }
}

// ---------------------------------------------------------------------------
// kernel_launch
// ---------------------------------------------------------------------------
extern "C" void kernel_launch(void* const* d_in, const int* in_sizes, int n_in,
                              void* d_out, int out_size)
{
    const float* hidden = (const float*)d_in[0];
    const float* wq = (const float*)d_in[1];
    const float* wk = (const float*)d_in[2];
    const float* wv = (const float*)d_in[3];
    const float* wo = (const float*)d_in[4];
    const float* bo = (const float*)d_in[5];
    float* out = (float*)d_out;
    (void)in_sizes; (void)n_in; (void)out_size;

    cudaFuncSetAttribute(qkv_gemm_tc, cudaFuncAttributeMaxDynamicSharedMemorySize,
                         GEMM_SMEM_BYTES);
    cudaFuncSetAttribute(out_gemm_tc, cudaFuncAttributeMaxDynamicSharedMemorySize,
                         GEMM_SMEM_BYTES);
    cudaFuncSetAttribute(flash_attn_tc, cudaFuncAttributeMaxDynamicSharedMemorySize,
                         ATT_SMEM_BYTES);

    // QKV projections (mma.sync tf32, double-buffered)
    qkv_gemm_tc<<<dim3(PE / BN, PM / BM, 3), 256, GEMM_SMEM_BYTES>>>(hidden, wq, wk, wv);

    // Attention (mma.sync tf32 flash, K/V double-buffered)
    flash_attn_tc<<<dim3(PS / 128, PBH), 256, ATT_SMEM_BYTES>>>();

    // Output projection (mma.sync tf32, double-buffered) + bias
    out_gemm_tc<<<dim3(PE / BN, PM / BM, 1), 256, GEMM_SMEM_BYTES>>>(wo, bo, out);
}

// round 8
// speedup vs baseline: 7.5241x; 2.1100x over previous
#include <cuda_runtime.h>
#include <cuda_fp16.h>
#include <cstdint>
#include <cstddef>

// Problem constants
#define PB 8
#define PS 1024
#define PE 1024
#define PH 16
#define PD 64
#define PM (PB * PS)        // 8192 GEMM rows
#define PBH (PB * PH)       // 128 (b,h) pairs

// ---------------------------------------------------------------------------
// fp16 scratch (static __device__, allocation-free per harness rules)
// ---------------------------------------------------------------------------
__device__ __half g_xh[PB * PS * PE];     // hidden_states fp16
__device__ __half g_wh[4 * PE * PE];      // wq(*1/32), wk, wv, wo fp16
__device__ __half g_qh[PB * PS * PE];
__device__ __half g_kh[PB * PS * PE];
__device__ __half g_vh[PB * PS * PE];
__device__ __half g_oh[PB * PS * PE];     // attention out (B,H,S,D) fp16

// ---------------------------------------------------------------------------
// PTX helpers
// ---------------------------------------------------------------------------
__device__ __forceinline__ uint32_t smem_u32(const void* p) {
    uint32_t a;
    asm("{ .reg .u64 t; cvta.to.shared.u64 t, %1; cvt.u32.u64 %0, t; }"
        : "=r"(a) : "l"(p));
    return a;
}

// fp16 MMA: D(16x8,f32) += A(16x16,f16) * B(16x8,f16)
__device__ __forceinline__ void mma_f16(float c[4], const uint32_t a[4],
                                        const uint32_t b[2]) {
    asm volatile(
        "mma.sync.aligned.m16n8k16.row.col.f32.f16.f16.f32 "
        "{%0,%1,%2,%3}, {%4,%5,%6,%7}, {%8,%9}, {%0,%1,%2,%3};"
        : "+f"(c[0]), "+f"(c[1]), "+f"(c[2]), "+f"(c[3])
        : "r"(a[0]), "r"(a[1]), "r"(a[2]), "r"(a[3]), "r"(b[0]), "r"(b[1]));
}

#define LDM_X4(r0, r1, r2, r3, addr) \
    asm volatile("ldmatrix.sync.aligned.m8n8.x4.shared.b16 {%0,%1,%2,%3}, [%4];" \
                 : "=r"(r0), "=r"(r1), "=r"(r2), "=r"(r3) : "r"(addr))
#define LDM_X4T(r0, r1, r2, r3, addr) \
    asm volatile("ldmatrix.sync.aligned.m8n8.x4.trans.shared.b16 {%0,%1,%2,%3}, [%4];" \
                 : "=r"(r0), "=r"(r1), "=r"(r2), "=r"(r3) : "r"(addr))

#define CP_ASYNC16(dst, src) \
    asm volatile("cp.async.cg.shared.global [%0], [%1], 16;" \
                 :: "r"(dst), "l"(src) : "memory")
#define CP_COMMIT()  asm volatile("cp.async.commit_group;" ::: "memory")
#define CP_WAIT1()   asm volatile("cp.async.wait_group 1;" ::: "memory")

__device__ __forceinline__ uint32_t f2h2u(float lo, float hi) {
    __half2 h = __floats2half2_rn(lo, hi);
    return *reinterpret_cast<uint32_t*>(&h);
}

// ---------------------------------------------------------------------------
// Prepass: fp32 -> fp16 conversion (scale folded into wq)
// ---------------------------------------------------------------------------
__global__ __launch_bounds__(256) void cvt_x(const float* __restrict__ x)
{
    const size_t i = ((size_t)blockIdx.x * 256 + threadIdx.x) * 8;
    const float4 a = *reinterpret_cast<const float4*>(x + i);
    const float4 b = *reinterpret_cast<const float4*>(x + i + 4);
    uint4 u;
    u.x = f2h2u(a.x, a.y); u.y = f2h2u(a.z, a.w);
    u.z = f2h2u(b.x, b.y); u.w = f2h2u(b.z, b.w);
    *reinterpret_cast<uint4*>(g_xh + i) = u;
}

__global__ __launch_bounds__(256) void cvt_w(const float* __restrict__ wq,
                                             const float* __restrict__ wk,
                                             const float* __restrict__ wv,
                                             const float* __restrict__ wo)
{
    const int z = blockIdx.y;
    const float* w = (z == 0) ? wq : (z == 1) ? wk : (z == 2) ? wv : wo;
    const float s = (z == 0) ? 0.03125f : 1.0f;   // fold E^-0.5 into Wq (exact)
    const size_t i = ((size_t)blockIdx.x * 256 + threadIdx.x) * 8;
    const float4 a = *reinterpret_cast<const float4*>(w + i);
    const float4 b = *reinterpret_cast<const float4*>(w + i + 4);
    uint4 u;
    u.x = f2h2u(a.x * s, a.y * s); u.y = f2h2u(a.z * s, a.w * s);
    u.z = f2h2u(b.x * s, b.y * s); u.w = f2h2u(b.z * s, b.w * s);
    *reinterpret_cast<uint4*>(g_wh + (size_t)z * PE * PE + i) = u;
}

// ---------------------------------------------------------------------------
// fp16 GEMM: C[8192,1024] = A[m][k] * W[k][n] (+bias). Block 128x256, KT=64,
// 8 warps (2m x 4n), warp tile 64x64. 3-stage cp.async pipeline, ldmatrix frags.
// A smem row = 64 halves + pad = 144 B (36 words, ≡4 mod 32: conflict-free).
// B smem row = 256 halves + pad = 528 B (132 words, ≡4 mod 32).
// PERM=true: A is the (B,H,S,D)->(B,S,E) permuted view of g_oh.
// ---------------------------------------------------------------------------
#define G_AROWB 144
#define G_BROWB 528
#define G_ASTAGE (128 * G_AROWB)            // 18432
#define G_BSTAGE (64 * G_BROWB)             // 33792
#define G_STAGE  (G_ASTAGE + G_BSTAGE)      // 52224
#define GEMM_SMEM_BYTES (3 * G_STAGE)       // 156672

template <bool PERM, bool HALF_OUT>
__device__ __forceinline__ void gemm_body(const __half* __restrict__ Ah,
                                          const __half* __restrict__ Wh,
                                          const float* __restrict__ bias,
                                          __half* __restrict__ Ch,
                                          float* __restrict__ Cf)
{
    extern __shared__ char smraw[];
    const uint32_t sbase = smem_u32(smraw);

    const int tid  = threadIdx.x;            // 256
    const int lane = tid & 31;
    const int wid  = tid >> 5;
    const int m0 = blockIdx.y * 128;
    const int n0 = blockIdx.x * 256;
    const int wr0 = (wid & 1) * 64;
    const int wn0 = (wid >> 1) * 64;
    const int g  = lane >> 2;
    const int t4 = lane & 3;
    const int mat = lane >> 3;
    const int lr  = lane & 7;

    // ldmatrix per-thread address components (byte offsets within stage)
    const uint32_t a_off = (uint32_t)((wr0 + (mat & 1) * 8 + lr) * G_AROWB
                                      + (mat >> 1) * 16);
    const uint32_t b_off = (uint32_t)(((mat & 1) * 8 + lr) * G_BROWB
                                      + (wn0 + (mat >> 1) * 8) * 2);

    float c[4][8][4];
#pragma unroll
    for (int mi = 0; mi < 4; mi++)
#pragma unroll
        for (int nj = 0; nj < 8; nj++)
#pragma unroll
            for (int e = 0; e < 4; e++) c[mi][nj][e] = 0.0f;

    auto issue = [&](int s, int kt) {
        const uint32_t As = sbase + (uint32_t)s * G_STAGE;
        const uint32_t Bs = As + G_ASTAGE;
#pragma unroll
        for (int i = 0; i < 4; i++) {       // A: 128 rows x 4 chunks
            const int id = i * 256 + tid;
            const int row = id >> 3;
            const int cc = (id & 7) * 8;
            const __half* src;
            if (PERM) {
                const int gm = m0 + row, gk = kt + cc;
                const int bb = gm >> 10, ss = gm & 1023;
                const int hh = gk >> 6,  dd = gk & 63;
                src = Ah + (((size_t)(bb * PH + hh)) * PS + ss) * PD + dd;
            } else {
                src = Ah + (size_t)(m0 + row) * PE + kt + cc;
            }
            CP_ASYNC16(As + row * G_AROWB + cc * 2, src);
        }
#pragma unroll
        for (int i = 0; i < 8; i++) {       // B: 64 rows x 32 chunks
            const int id = i * 256 + tid;
            const int row = id >> 5;
            const int cc = (id & 31) * 8;
            CP_ASYNC16(Bs + row * G_BROWB + cc * 2,
                       Wh + (size_t)(kt + row) * PE + n0 + cc);
        }
    };

    issue(0, 0);  CP_COMMIT();
    issue(1, 64); CP_COMMIT();

    for (int it = 0; it < 16; it++) {
        CP_WAIT1();
        __syncthreads();
        if (it + 2 < 16) issue((it + 2) % 3, (it + 2) * 64);
        CP_COMMIT();

        const uint32_t As = sbase + (uint32_t)(it % 3) * G_STAGE;
        const uint32_t Bs = As + G_ASTAGE;

#pragma unroll
        for (int k16 = 0; k16 < 64; k16 += 16) {
            uint32_t af[4][4], bf[8][2];
#pragma unroll
            for (int mi = 0; mi < 4; mi++)
                LDM_X4(af[mi][0], af[mi][1], af[mi][2], af[mi][3],
                       As + a_off + mi * (16 * G_AROWB) + k16 * 2);
#pragma unroll
            for (int p = 0; p < 4; p++)
                LDM_X4T(bf[2 * p][0], bf[2 * p][1], bf[2 * p + 1][0], bf[2 * p + 1][1],
                        Bs + b_off + k16 * G_BROWB + p * 32);
#pragma unroll
            for (int mi = 0; mi < 4; mi++)
#pragma unroll
                for (int nj = 0; nj < 8; nj++)
                    mma_f16(c[mi][nj], af[mi], bf[nj]);
        }
    }

    // Epilogue
#pragma unroll
    for (int mi = 0; mi < 4; mi++) {
        const int r = m0 + wr0 + mi * 16 + g;
#pragma unroll
        for (int nj = 0; nj < 8; nj++) {
            const int cg = n0 + wn0 + nj * 8 + 2 * t4;
            if (HALF_OUT) {
                *reinterpret_cast<__half2*>(&Ch[(size_t)r * PE + cg]) =
                    __floats2half2_rn(c[mi][nj][0], c[mi][nj][1]);
                *reinterpret_cast<__half2*>(&Ch[(size_t)(r + 8) * PE + cg]) =
                    __floats2half2_rn(c[mi][nj][2], c[mi][nj][3]);
            } else {
                const float b0 = bias[cg], b1 = bias[cg + 1];
                float2 v0, v1;
                v0.x = c[mi][nj][0] + b0; v0.y = c[mi][nj][1] + b1;
                v1.x = c[mi][nj][2] + b0; v1.y = c[mi][nj][3] + b1;
                *reinterpret_cast<float2*>(&Cf[(size_t)r * PE + cg]) = v0;
                *reinterpret_cast<float2*>(&Cf[(size_t)(r + 8) * PE + cg]) = v1;
            }
        }
    }
}

__global__ __launch_bounds__(256, 1) void qkv_gemm_h()
{
    const int z = blockIdx.z;
    __half* C = (z == 0) ? g_qh : (z == 1) ? g_kh : g_vh;
    gemm_body<false, true>(g_xh, g_wh + (size_t)z * PE * PE, nullptr, C, nullptr);
}

__global__ __launch_bounds__(256, 1) void out_gemm_h(const float* __restrict__ bo,
                                                     float* __restrict__ out)
{
    gemm_body<true, false>(g_oh, g_wh + 3 * (size_t)PE * PE, bo, nullptr, out);
}

// ---------------------------------------------------------------------------
// fp16 flash attention. Br=128, Bc=64, 256 threads = 8 warps x 16 q rows.
// grid (8, 128). Q staged once; K/V 3-stage cp.async. All smem rows 144 B.
// Layout (bytes): Qs[0,18432) | 3 stages x (K 9216 + V 9216) | Ps[73728,92160).
// ---------------------------------------------------------------------------
#define ATT_ROWB 144
#define ATT_KV_STAGE (64 * ATT_ROWB * 2)    // 18432
#define ATT_PS_OFF (18432 + 3 * ATT_KV_STAGE)
#define ATT_SMEM_BYTES (ATT_PS_OFF + 128 * ATT_ROWB)   // 92160

__global__ __launch_bounds__(256, 2) void flash_attn_h()
{
    extern __shared__ char smraw[];
    const uint32_t sbase = smem_u32(smraw);
    const uint32_t Qs = sbase;
    const uint32_t Ps = sbase + ATT_PS_OFF;

    const int tid  = threadIdx.x;
    const int lane = tid & 31;
    const int wid  = tid >> 5;
    const int g  = lane >> 2;
    const int t4 = lane & 3;
    const int mat = lane >> 3;
    const int lr  = lane & 7;
    const int bh = blockIdx.y;
    const int q0 = blockIdx.x * 128;
    const int wr = wid * 16;

    const __half* Qg = g_qh + (size_t)bh * PS * PD;
    const __half* Kg = g_kh + (size_t)bh * PS * PD;
    const __half* Vg = g_vh + (size_t)bh * PS * PD;

    // ldmatrix address components (byte offsets)
    const uint32_t qa_off = (uint32_t)((wr + (mat & 1) * 8 + lr) * ATT_ROWB
                                       + (mat >> 1) * 16);       // + k16*2, off Qs/Ps
    const uint32_t kb_off = (uint32_t)(((mat >> 1) * 8 + lr) * ATT_ROWB
                                       + (mat & 1) * 16);        // + p*2304 + k16*2
    const uint32_t vb_off = (uint32_t)(((mat & 1) * 8 + lr) * ATT_ROWB
                                       + (mat >> 1) * 16);       // + k16*144 + p*32

    auto issueKV = [&](int s, int t) {
        const uint32_t Ks = sbase + 18432 + (uint32_t)s * ATT_KV_STAGE;
        const uint32_t Vs = Ks + 64 * ATT_ROWB;
#pragma unroll
        for (int i = 0; i < 2; i++) {
            const int id = i * 256 + tid;
            const int row = id >> 3;
            const int cc = (id & 7) * 8;
            CP_ASYNC16(Ks + row * ATT_ROWB + cc * 2,
                       Kg + (size_t)(t * 64 + row) * PD + cc);
            CP_ASYNC16(Vs + row * ATT_ROWB + cc * 2,
                       Vg + (size_t)(t * 64 + row) * PD + cc);
        }
    };

    // Prologue: Q + K/V tile 0 in group 0; K/V tile 1 in group 1
#pragma unroll
    for (int i = 0; i < 4; i++) {
        const int id = i * 256 + tid;
        const int row = id >> 3;
        const int cc = (id & 7) * 8;
        CP_ASYNC16(Qs + row * ATT_ROWB + cc * 2,
                   Qg + (size_t)(q0 + row) * PD + cc);
    }
    issueKV(0, 0); CP_COMMIT();
    issueKV(1, 1); CP_COMMIT();

    float m_i[2] = {-1e30f, -1e30f};
    float l_i[2] = {0.0f, 0.0f};
    float o[8][4];
#pragma unroll
    for (int nj = 0; nj < 8; nj++)
#pragma unroll
        for (int e = 0; e < 4; e++) o[nj][e] = 0.0f;

    for (int t = 0; t < 16; t++) {
        CP_WAIT1();
        __syncthreads();
        if (t + 2 < 16) issueKV((t + 2) % 3, t + 2);
        CP_COMMIT();

        const uint32_t Ks = sbase + 18432 + (uint32_t)(t % 3) * ATT_KV_STAGE;
        const uint32_t Vs = Ks + 64 * ATT_ROWB;

        // ---- S = Q Kt ----
        float s[8][4];
#pragma unroll
        for (int nj = 0; nj < 8; nj++)
#pragma unroll
            for (int e = 0; e < 4; e++) s[nj][e] = 0.0f;

#pragma unroll
        for (int k16 = 0; k16 < 64; k16 += 16) {
            uint32_t qf[4], kf[8][2];
            LDM_X4(qf[0], qf[1], qf[2], qf[3], Qs + qa_off + k16 * 2);
#pragma unroll
            for (int p = 0; p < 4; p++)
                LDM_X4(kf[2 * p][0], kf[2 * p][1], kf[2 * p + 1][0], kf[2 * p + 1][1],
                       Ks + kb_off + p * (16 * ATT_ROWB) + k16 * 2);
#pragma unroll
            for (int nj = 0; nj < 8; nj++)
                mma_f16(s[nj], qf, kf[nj]);
        }

        // ---- online softmax (rows g, g+8; quad reduction over t4) ----
        float mx0 = s[0][0], mx1 = s[0][2];
#pragma unroll
        for (int nj = 0; nj < 8; nj++) {
            mx0 = fmaxf(mx0, fmaxf(s[nj][0], s[nj][1]));
            mx1 = fmaxf(mx1, fmaxf(s[nj][2], s[nj][3]));
        }
#pragma unroll
        for (int off = 1; off <= 2; off <<= 1) {
            mx0 = fmaxf(mx0, __shfl_xor_sync(0xffffffffu, mx0, off));
            mx1 = fmaxf(mx1, __shfl_xor_sync(0xffffffffu, mx1, off));
        }

        const float mn0 = fmaxf(m_i[0], mx0);
        const float mn1 = fmaxf(m_i[1], mx1);
        const float al0 = __expf(m_i[0] - mn0);
        const float al1 = __expf(m_i[1] - mn1);
        m_i[0] = mn0; m_i[1] = mn1;

        float ls0 = 0.0f, ls1 = 0.0f;
#pragma unroll
        for (int nj = 0; nj < 8; nj++) {
            s[nj][0] = __expf(s[nj][0] - mn0);
            s[nj][1] = __expf(s[nj][1] - mn0);
            s[nj][2] = __expf(s[nj][2] - mn1);
            s[nj][3] = __expf(s[nj][3] - mn1);
            ls0 += s[nj][0] + s[nj][1];
            ls1 += s[nj][2] + s[nj][3];
        }
#pragma unroll
        for (int off = 1; off <= 2; off <<= 1) {
            ls0 += __shfl_xor_sync(0xffffffffu, ls0, off);
            ls1 += __shfl_xor_sync(0xffffffffu, ls1, off);
        }
        l_i[0] = l_i[0] * al0 + ls0;
        l_i[1] = l_i[1] * al1 + ls1;

#pragma unroll
        for (int nj = 0; nj < 8; nj++) {
            o[nj][0] *= al0; o[nj][1] *= al0;
            o[nj][2] *= al1; o[nj][3] *= al1;
        }

        // ---- P (fp16) -> warp-private smem rows ----
#pragma unroll
        for (int nj = 0; nj < 8; nj++) {
            const uint32_t pc = (nj * 8 + 2 * t4) * 2;
            *reinterpret_cast<__half2*>(
                (char*)nullptr + 0) ;  // placeholder avoided below
        }
        // (write via smem addresses)
#pragma unroll
        for (int nj = 0; nj < 8; nj++) {
            const uint32_t c0b = (uint32_t)((nj * 8 + 2 * t4) * 2);
            const uint32_t r0b = Ps + (wr + g) * ATT_ROWB + c0b;
            const uint32_t r1b = Ps + (wr + g + 8) * ATT_ROWB + c0b;
            const uint32_t p0 = f2h2u(s[nj][0], s[nj][1]);
            const uint32_t p1 = f2h2u(s[nj][2], s[nj][3]);
            asm volatile("st.shared.b32 [%0], %1;" :: "r"(r0b), "r"(p0) : "memory");
            asm volatile("st.shared.b32 [%0], %1;" :: "r"(r1b), "r"(p1) : "memory");
        }
        __syncwarp();

        // ---- O += P V ----
#pragma unroll
        for (int k16 = 0; k16 < 64; k16 += 16) {
            uint32_t pf[4], vf[8][2];
            LDM_X4(pf[0], pf[1], pf[2], pf[3], Ps + qa_off + k16 * 2);
#pragma unroll
            for (int p = 0; p < 4; p++)
                LDM_X4T(vf[2 * p][0], vf[2 * p][1], vf[2 * p + 1][0], vf[2 * p + 1][1],
                        Vs + vb_off + k16 * ATT_ROWB + p * 32);
#pragma unroll
            for (int nj = 0; nj < 8; nj++)
                mma_f16(o[nj], pf, vf[nj]);
        }
        __syncwarp();   // Ps reads complete before next tile overwrites
    }

    // ---- epilogue: normalize, fp16 store to g_oh ----
    const float inv0 = 1.0f / l_i[0];
    const float inv1 = 1.0f / l_i[1];
    __half* Op = g_oh + (size_t)bh * PS * PD;
#pragma unroll
    for (int nj = 0; nj < 8; nj++) {
        const int cg = nj * 8 + 2 * t4;
        *reinterpret_cast<__half2*>(&Op[(size_t)(q0 + wr + g) * PD + cg]) =
            __floats2half2_rn(o[nj][0] * inv0, o[nj][1] * inv0);
        *reinterpret_cast<__half2*>(&Op[(size_t)(q0 + wr + g + 8) * PD + cg]) =
            __floats2half2_rn(o[nj][2] * inv1, o[nj][3] * inv1);
    }
}

// ---------------------------------------------------------------------------
// kernel_launch
// ---------------------------------------------------------------------------
extern "C" void kernel_launch(void* const* d_in, const int* in_sizes, int n_in,
                              void* d_out, int out_size)
{
    const float* hidden = (const float*)d_in[0];
    const float* wq = (const float*)d_in[1];
    const float* wk = (const float*)d_in[2];
    const float* wv = (const float*)d_in[3];
    const float* wo = (const float*)d_in[4];
    const float* bo = (const float*)d_in[5];
    float* out = (float*)d_out;
    (void)in_sizes; (void)n_in; (void)out_size;

    cudaFuncSetAttribute(qkv_gemm_h, cudaFuncAttributeMaxDynamicSharedMemorySize,
                         GEMM_SMEM_BYTES);
    cudaFuncSetAttribute(out_gemm_h, cudaFuncAttributeMaxDynamicSharedMemorySize,
                         GEMM_SMEM_BYTES);
    cudaFuncSetAttribute(flash_attn_h, cudaFuncAttributeMaxDynamicSharedMemorySize,
                         ATT_SMEM_BYTES);

    // Prepass: fp32 -> fp16 (scale folded into Wq)
    cvt_x<<<(PB * PS * PE) / (256 * 8), 256>>>(hidden);
    cvt_w<<<dim3((PE * PE) / (256 * 8), 4), 256>>>(wq, wk, wv, wo);

    // QKV projections (fp16 mma, cp.async 3-stage)
    qkv_gemm_h<<<dim3(PE / 256, PM / 128, 3), 256, GEMM_SMEM_BYTES>>>();

    // Attention (fp16 mma flash)
    flash_attn_h<<<dim3(PS / 128, PBH), 256, ATT_SMEM_BYTES>>>();

    // Output projection (fp16 mma) + fp32 bias/out
    out_gemm_h<<<dim3(PE / 256, PM / 128, 1), 256, GEMM_SMEM_BYTES>>>(bo, out);
}

// round 9
// speedup vs baseline: 8.0288x; 1.0671x over previous
#include <cuda_runtime.h>
#include <cuda_fp16.h>
#include <cstdint>
#include <cstddef>

// Problem constants
#define PB 8
#define PS 1024
#define PE 1024
#define PH 16
#define PD 64
#define PM (PB * PS)        // 8192 GEMM rows
#define PBH (PB * PH)       // 128 (b,h) pairs

// ---------------------------------------------------------------------------
// fp16 scratch (static __device__, allocation-free per harness rules)
// ---------------------------------------------------------------------------
__device__ __half g_xh[PB * PS * PE];     // hidden_states fp16
__device__ __half g_wh[4 * PE * PE];      // wq(*scale*log2e), wk, wv, wo fp16
__device__ __half g_qh[PB * PS * PE];
__device__ __half g_kh[PB * PS * PE];
__device__ __half g_vh[PB * PS * PE];
__device__ __half g_oh[PB * PS * PE];     // attention out (B,H,S,D) fp16

// ---------------------------------------------------------------------------
// PTX helpers
// ---------------------------------------------------------------------------
__device__ __forceinline__ uint32_t smem_u32(const void* p) {
    uint32_t a;
    asm("{ .reg .u64 t; cvta.to.shared.u64 t, %1; cvt.u32.u64 %0, t; }"
        : "=r"(a) : "l"(p));
    return a;
}

// fp16 MMA: D(16x8,f32) += A(16x16,f16) * B(16x8,f16)
__device__ __forceinline__ void mma_f16(float c[4], const uint32_t a[4],
                                        const uint32_t b[2]) {
    asm volatile(
        "mma.sync.aligned.m16n8k16.row.col.f32.f16.f16.f32 "
        "{%0,%1,%2,%3}, {%4,%5,%6,%7}, {%8,%9}, {%0,%1,%2,%3};"
        : "+f"(c[0]), "+f"(c[1]), "+f"(c[2]), "+f"(c[3])
        : "r"(a[0]), "r"(a[1]), "r"(a[2]), "r"(a[3]), "r"(b[0]), "r"(b[1]));
}

#define LDM_X4(r0, r1, r2, r3, addr) \
    asm volatile("ldmatrix.sync.aligned.m8n8.x4.shared.b16 {%0,%1,%2,%3}, [%4];" \
                 : "=r"(r0), "=r"(r1), "=r"(r2), "=r"(r3) : "r"(addr))
#define LDM_X4T(r0, r1, r2, r3, addr) \
    asm volatile("ldmatrix.sync.aligned.m8n8.x4.trans.shared.b16 {%0,%1,%2,%3}, [%4];" \
                 : "=r"(r0), "=r"(r1), "=r"(r2), "=r"(r3) : "r"(addr))

#define CP_ASYNC16(dst, src) \
    asm volatile("cp.async.cg.shared.global [%0], [%1], 16;" \
                 :: "r"(dst), "l"(src) : "memory")
#define CP_COMMIT()  asm volatile("cp.async.commit_group;" ::: "memory")
#define CP_WAIT1()   asm volatile("cp.async.wait_group 1;" ::: "memory")

__device__ __forceinline__ uint32_t f2h2u(float lo, float hi) {
    __half2 h = __floats2half2_rn(lo, hi);
    return *reinterpret_cast<uint32_t*>(&h);
}

__device__ __forceinline__ float ex2(float x) {
    float y;
    asm("ex2.approx.ftz.f32 %0, %1;" : "=f"(y) : "f"(x));
    return y;
}

// ---------------------------------------------------------------------------
// Prepass: fp32 -> fp16 conversion (attention scale * log2e folded into wq)
// ---------------------------------------------------------------------------
__global__ __launch_bounds__(256) void cvt_x(const float* __restrict__ x)
{
    const size_t i = ((size_t)blockIdx.x * 256 + threadIdx.x) * 8;
    const float4 a = *reinterpret_cast<const float4*>(x + i);
    const float4 b = *reinterpret_cast<const float4*>(x + i + 4);
    uint4 u;
    u.x = f2h2u(a.x, a.y); u.y = f2h2u(a.z, a.w);
    u.z = f2h2u(b.x, b.y); u.w = f2h2u(b.z, b.w);
    *reinterpret_cast<uint4*>(g_xh + i) = u;
}

__global__ __launch_bounds__(256) void cvt_w(const float* __restrict__ wq,
                                             const float* __restrict__ wk,
                                             const float* __restrict__ wv,
                                             const float* __restrict__ wo)
{
    const int z = blockIdx.y;
    const float* w = (z == 0) ? wq : (z == 1) ? wk : (z == 2) ? wv : wo;
    // Fold E^-0.5 * log2(e) into Wq: softmax then runs in the exp2 domain.
    const float s = (z == 0) ? 0.03125f * 1.4426950408889634f : 1.0f;
    const size_t i = ((size_t)blockIdx.x * 256 + threadIdx.x) * 8;
    const float4 a = *reinterpret_cast<const float4*>(w + i);
    const float4 b = *reinterpret_cast<const float4*>(w + i + 4);
    uint4 u;
    u.x = f2h2u(a.x * s, a.y * s); u.y = f2h2u(a.z * s, a.w * s);
    u.z = f2h2u(b.x * s, b.y * s); u.w = f2h2u(b.z * s, b.w * s);
    *reinterpret_cast<uint4*>(g_wh + (size_t)z * PE * PE + i) = u;
}

// ---------------------------------------------------------------------------
// fp16 GEMM (unchanged from R8): C[8192,1024] = A*W (+bias). Block 128x256,
// KT=64, 8 warps (2m x 4n), warp tile 64x64, 3-stage cp.async, ldmatrix.
// ---------------------------------------------------------------------------
#define G_AROWB 144
#define G_BROWB 528
#define G_ASTAGE (128 * G_AROWB)            // 18432
#define G_BSTAGE (64 * G_BROWB)             // 33792
#define G_STAGE  (G_ASTAGE + G_BSTAGE)      // 52224
#define GEMM_SMEM_BYTES (3 * G_STAGE)       // 156672

template <bool PERM, bool HALF_OUT>
__device__ __forceinline__ void gemm_body(const __half* __restrict__ Ah,
                                          const __half* __restrict__ Wh,
                                          const float* __restrict__ bias,
                                          __half* __restrict__ Ch,
                                          float* __restrict__ Cf)
{
    extern __shared__ char smraw[];
    const uint32_t sbase = smem_u32(smraw);

    const int tid  = threadIdx.x;            // 256
    const int lane = tid & 31;
    const int wid  = tid >> 5;
    const int m0 = blockIdx.y * 128;
    const int n0 = blockIdx.x * 256;
    const int wr0 = (wid & 1) * 64;
    const int wn0 = (wid >> 1) * 64;
    const int g  = lane >> 2;
    const int t4 = lane & 3;
    const int mat = lane >> 3;
    const int lr  = lane & 7;

    const uint32_t a_off = (uint32_t)((wr0 + (mat & 1) * 8 + lr) * G_AROWB
                                      + (mat >> 1) * 16);
    const uint32_t b_off = (uint32_t)(((mat & 1) * 8 + lr) * G_BROWB
                                      + (wn0 + (mat >> 1) * 8) * 2);

    float c[4][8][4];
#pragma unroll
    for (int mi = 0; mi < 4; mi++)
#pragma unroll
        for (int nj = 0; nj < 8; nj++)
#pragma unroll
            for (int e = 0; e < 4; e++) c[mi][nj][e] = 0.0f;

    auto issue = [&](int s, int kt) {
        const uint32_t As = sbase + (uint32_t)s * G_STAGE;
        const uint32_t Bs = As + G_ASTAGE;
#pragma unroll
        for (int i = 0; i < 4; i++) {
            const int id = i * 256 + tid;
            const int row = id >> 3;
            const int cc = (id & 7) * 8;
            const __half* src;
            if (PERM) {
                const int gm = m0 + row, gk = kt + cc;
                const int bb = gm >> 10, ss = gm & 1023;
                const int hh = gk >> 6,  dd = gk & 63;
                src = Ah + (((size_t)(bb * PH + hh)) * PS + ss) * PD + dd;
            } else {
                src = Ah + (size_t)(m0 + row) * PE + kt + cc;
            }
            CP_ASYNC16(As + row * G_AROWB + cc * 2, src);
        }
#pragma unroll
        for (int i = 0; i < 8; i++) {
            const int id = i * 256 + tid;
            const int row = id >> 5;
            const int cc = (id & 31) * 8;
            CP_ASYNC16(Bs + row * G_BROWB + cc * 2,
                       Wh + (size_t)(kt + row) * PE + n0 + cc);
        }
    };

    issue(0, 0);  CP_COMMIT();
    issue(1, 64); CP_COMMIT();

    for (int it = 0; it < 16; it++) {
        CP_WAIT1();
        __syncthreads();
        if (it + 2 < 16) issue((it + 2) % 3, (it + 2) * 64);
        CP_COMMIT();

        const uint32_t As = sbase + (uint32_t)(it % 3) * G_STAGE;
        const uint32_t Bs = As + G_ASTAGE;

#pragma unroll
        for (int k16 = 0; k16 < 64; k16 += 16) {
            uint32_t af[4][4], bf[8][2];
#pragma unroll
            for (int mi = 0; mi < 4; mi++)
                LDM_X4(af[mi][0], af[mi][1], af[mi][2], af[mi][3],
                       As + a_off + mi * (16 * G_AROWB) + k16 * 2);
#pragma unroll
            for (int p = 0; p < 4; p++)
                LDM_X4T(bf[2 * p][0], bf[2 * p][1], bf[2 * p + 1][0], bf[2 * p + 1][1],
                        Bs + b_off + k16 * G_BROWB + p * 32);
#pragma unroll
            for (int mi = 0; mi < 4; mi++)
#pragma unroll
                for (int nj = 0; nj < 8; nj++)
                    mma_f16(c[mi][nj], af[mi], bf[nj]);
        }
    }

#pragma unroll
    for (int mi = 0; mi < 4; mi++) {
        const int r = m0 + wr0 + mi * 16 + g;
#pragma unroll
        for (int nj = 0; nj < 8; nj++) {
            const int cg = n0 + wn0 + nj * 8 + 2 * t4;
            if (HALF_OUT) {
                *reinterpret_cast<__half2*>(&Ch[(size_t)r * PE + cg]) =
                    __floats2half2_rn(c[mi][nj][0], c[mi][nj][1]);
                *reinterpret_cast<__half2*>(&Ch[(size_t)(r + 8) * PE + cg]) =
                    __floats2half2_rn(c[mi][nj][2], c[mi][nj][3]);
            } else {
                const float b0 = bias[cg], b1 = bias[cg + 1];
                float2 v0, v1;
                v0.x = c[mi][nj][0] + b0; v0.y = c[mi][nj][1] + b1;
                v1.x = c[mi][nj][2] + b0; v1.y = c[mi][nj][3] + b1;
                *reinterpret_cast<float2*>(&Cf[(size_t)r * PE + cg]) = v0;
                *reinterpret_cast<float2*>(&Cf[(size_t)(r + 8) * PE + cg]) = v1;
            }
        }
    }
}

__global__ __launch_bounds__(256, 1) void qkv_gemm_h()
{
    const int z = blockIdx.z;
    __half* C = (z == 0) ? g_qh : (z == 1) ? g_kh : g_vh;
    gemm_body<false, true>(g_xh, g_wh + (size_t)z * PE * PE, nullptr, C, nullptr);
}

__global__ __launch_bounds__(256, 1) void out_gemm_h(const float* __restrict__ bo,
                                                     float* __restrict__ out)
{
    gemm_body<true, false>(g_oh, g_wh + 3 * (size_t)PE * PE, bo, nullptr, out);
}

// ---------------------------------------------------------------------------
// fp16 flash attention, register-resident P and hoisted Q fragments.
// Br=128, Bc=64, 256 threads = 8 warps x 16 q rows. grid (8, 128).
// Q staged once -> fragments held in registers for all 16 K-tiles.
// P: S C-fragments convert in-register to PV A-fragments (no smem round trip).
// Softmax in exp2 domain (log2e folded into Wq).
// Smem: Qs 18432 + 3 stages x (K 9216 + V 9216) = 73728 B.
// ---------------------------------------------------------------------------
#define ATT_ROWB 144
#define ATT_KV_STAGE (64 * ATT_ROWB * 2)    // 18432
#define ATT_SMEM_BYTES (18432 + 3 * ATT_KV_STAGE)   // 73728

__global__ __launch_bounds__(256, 2) void flash_attn_h()
{
    extern __shared__ char smraw[];
    const uint32_t sbase = smem_u32(smraw);
    const uint32_t Qs = sbase;

    const int tid  = threadIdx.x;
    const int lane = tid & 31;
    const int wid  = tid >> 5;
    const int g  = lane >> 2;
    const int t4 = lane & 3;
    const int mat = lane >> 3;
    const int lr  = lane & 7;
    const int bh = blockIdx.y;
    const int q0 = blockIdx.x * 128;
    const int wr = wid * 16;

    const __half* Qg = g_qh + (size_t)bh * PS * PD;
    const __half* Kg = g_kh + (size_t)bh * PS * PD;
    const __half* Vg = g_vh + (size_t)bh * PS * PD;

    const uint32_t qa_off = (uint32_t)((wr + (mat & 1) * 8 + lr) * ATT_ROWB
                                       + (mat >> 1) * 16);
    const uint32_t kb_off = (uint32_t)(((mat >> 1) * 8 + lr) * ATT_ROWB
                                       + (mat & 1) * 16);
    const uint32_t vb_off = (uint32_t)(((mat & 1) * 8 + lr) * ATT_ROWB
                                       + (mat >> 1) * 16);

    auto issueKV = [&](int s, int t) {
        const uint32_t Ks = sbase + 18432 + (uint32_t)s * ATT_KV_STAGE;
        const uint32_t Vs = Ks + 64 * ATT_ROWB;
#pragma unroll
        for (int i = 0; i < 2; i++) {
            const int id = i * 256 + tid;
            const int row = id >> 3;
            const int cc = (id & 7) * 8;
            CP_ASYNC16(Ks + row * ATT_ROWB + cc * 2,
                       Kg + (size_t)(t * 64 + row) * PD + cc);
            CP_ASYNC16(Vs + row * ATT_ROWB + cc * 2,
                       Vg + (size_t)(t * 64 + row) * PD + cc);
        }
    };

    // Prologue: Q + K/V tile 0 in group 0; K/V tile 1 in group 1
#pragma unroll
    for (int i = 0; i < 4; i++) {
        const int id = i * 256 + tid;
        const int row = id >> 3;
        const int cc = (id & 7) * 8;
        CP_ASYNC16(Qs + row * ATT_ROWB + cc * 2,
                   Qg + (size_t)(q0 + row) * PD + cc);
    }
    issueKV(0, 0); CP_COMMIT();
    issueKV(1, 1); CP_COMMIT();

    // Wait for group 0 (Q + KV0), hoist Q fragments into registers
    CP_WAIT1();
    __syncthreads();
    uint32_t qf[4][4];
#pragma unroll
    for (int kk = 0; kk < 4; kk++)
        LDM_X4(qf[kk][0], qf[kk][1], qf[kk][2], qf[kk][3],
               Qs + qa_off + kk * 32);

    float m_i[2] = {-1e30f, -1e30f};
    float l_i[2] = {0.0f, 0.0f};
    float o[8][4];
#pragma unroll
    for (int nj = 0; nj < 8; nj++)
#pragma unroll
        for (int e = 0; e < 4; e++) o[nj][e] = 0.0f;

    for (int t = 0; t < 16; t++) {
        if (t > 0) { CP_WAIT1(); __syncthreads(); }
        if (t + 2 < 16) issueKV((t + 2) % 3, t + 2);
        CP_COMMIT();

        const uint32_t Ks = sbase + 18432 + (uint32_t)(t % 3) * ATT_KV_STAGE;
        const uint32_t Vs = Ks + 64 * ATT_ROWB;

        // ---- S = Q Kt (Q from registers) ----
        float s[8][4];
#pragma unroll
        for (int nj = 0; nj < 8; nj++)
#pragma unroll
            for (int e = 0; e < 4; e++) s[nj][e] = 0.0f;

#pragma unroll
        for (int kk = 0; kk < 4; kk++) {
            uint32_t kf[8][2];
#pragma unroll
            for (int p = 0; p < 4; p++)
                LDM_X4(kf[2 * p][0], kf[2 * p][1], kf[2 * p + 1][0], kf[2 * p + 1][1],
                       Ks + kb_off + p * (16 * ATT_ROWB) + kk * 32);
#pragma unroll
            for (int nj = 0; nj < 8; nj++)
                mma_f16(s[nj], qf[kk], kf[nj]);
        }

        // ---- online softmax in exp2 domain (rows g, g+8) ----
        float mx0 = s[0][0], mx1 = s[0][2];
#pragma unroll
        for (int nj = 0; nj < 8; nj++) {
            mx0 = fmaxf(mx0, fmaxf(s[nj][0], s[nj][1]));
            mx1 = fmaxf(mx1, fmaxf(s[nj][2], s[nj][3]));
        }
#pragma unroll
        for (int off = 1; off <= 2; off <<= 1) {
            mx0 = fmaxf(mx0, __shfl_xor_sync(0xffffffffu, mx0, off));
            mx1 = fmaxf(mx1, __shfl_xor_sync(0xffffffffu, mx1, off));
        }

        const float mn0 = fmaxf(m_i[0], mx0);
        const float mn1 = fmaxf(m_i[1], mx1);
        const float al0 = ex2(m_i[0] - mn0);
        const float al1 = ex2(m_i[1] - mn1);
        m_i[0] = mn0; m_i[1] = mn1;

        float ls0 = 0.0f, ls1 = 0.0f;
#pragma unroll
        for (int nj = 0; nj < 8; nj++) {
            s[nj][0] = ex2(s[nj][0] - mn0);
            s[nj][1] = ex2(s[nj][1] - mn0);
            s[nj][2] = ex2(s[nj][2] - mn1);
            s[nj][3] = ex2(s[nj][3] - mn1);
            ls0 += s[nj][0] + s[nj][1];
            ls1 += s[nj][2] + s[nj][3];
        }
#pragma unroll
        for (int off = 1; off <= 2; off <<= 1) {
            ls0 += __shfl_xor_sync(0xffffffffu, ls0, off);
            ls1 += __shfl_xor_sync(0xffffffffu, ls1, off);
        }
        l_i[0] = l_i[0] * al0 + ls0;
        l_i[1] = l_i[1] * al1 + ls1;

#pragma unroll
        for (int nj = 0; nj < 8; nj++) {
            o[nj][0] *= al0; o[nj][1] *= al0;
            o[nj][2] *= al1; o[nj][3] *= al1;
        }

        // ---- O += P V : P converts C-frag -> A-frag in registers ----
#pragma unroll
        for (int kk = 0; kk < 4; kk++) {
            uint32_t pf[4];
            pf[0] = f2h2u(s[2 * kk][0],     s[2 * kk][1]);
            pf[1] = f2h2u(s[2 * kk][2],     s[2 * kk][3]);
            pf[2] = f2h2u(s[2 * kk + 1][0], s[2 * kk + 1][1]);
            pf[3] = f2h2u(s[2 * kk + 1][2], s[2 * kk + 1][3]);
            uint32_t vf[8][2];
#pragma unroll
            for (int p = 0; p < 4; p++)
                LDM_X4T(vf[2 * p][0], vf[2 * p][1], vf[2 * p + 1][0], vf[2 * p + 1][1],
                        Vs + vb_off + kk * (16 * ATT_ROWB) + p * 32);
#pragma unroll
            for (int nj = 0; nj < 8; nj++)
                mma_f16(o[nj], pf, vf[nj]);
        }
    }

    // ---- epilogue: normalize, fp16 store to g_oh ----
    const float inv0 = 1.0f / l_i[0];
    const float inv1 = 1.0f / l_i[1];
    __half* Op = g_oh + (size_t)bh * PS * PD;
#pragma unroll
    for (int nj = 0; nj < 8; nj++) {
        const int cg = nj * 8 + 2 * t4;
        *reinterpret_cast<__half2*>(&Op[(size_t)(q0 + wr + g) * PD + cg]) =
            __floats2half2_rn(o[nj][0] * inv0, o[nj][1] * inv0);
        *reinterpret_cast<__half2*>(&Op[(size_t)(q0 + wr + g + 8) * PD + cg]) =
            __floats2half2_rn(o[nj][2] * inv1, o[nj][3] * inv1);
    }
}

// ---------------------------------------------------------------------------
// kernel_launch
// ---------------------------------------------------------------------------
extern "C" void kernel_launch(void* const* d_in, const int* in_sizes, int n_in,
                              void* d_out, int out_size)
{
    const float* hidden = (const float*)d_in[0];
    const float* wq = (const float*)d_in[1];
    const float* wk = (const float*)d_in[2];
    const float* wv = (const float*)d_in[3];
    const float* wo = (const float*)d_in[4];
    const float* bo = (const float*)d_in[5];
    float* out = (float*)d_out;
    (void)in_sizes; (void)n_in; (void)out_size;

    cudaFuncSetAttribute(qkv_gemm_h, cudaFuncAttributeMaxDynamicSharedMemorySize,
                         GEMM_SMEM_BYTES);
    cudaFuncSetAttribute(out_gemm_h, cudaFuncAttributeMaxDynamicSharedMemorySize,
                         GEMM_SMEM_BYTES);
    cudaFuncSetAttribute(flash_attn_h, cudaFuncAttributeMaxDynamicSharedMemorySize,
                         ATT_SMEM_BYTES);

    // Prepass: fp32 -> fp16 (scale * log2e folded into Wq)
    cvt_x<<<(PB * PS * PE) / (256 * 8), 256>>>(hidden);
    cvt_w<<<dim3((PE * PE) / (256 * 8), 4), 256>>>(wq, wk, wv, wo);

    // QKV projections (fp16 mma, cp.async 3-stage)
    qkv_gemm_h<<<dim3(PE / 256, PM / 128, 3), 256, GEMM_SMEM_BYTES>>>();

    // Attention (fp16 mma flash, register P)
    flash_attn_h<<<dim3(PS / 128, PBH), 256, ATT_SMEM_BYTES>>>();

    // Output projection (fp16 mma) + fp32 bias/out
    out_gemm_h<<<dim3(PE / 256, PM / 128, 1), 256, GEMM_SMEM_BYTES>>>(bo, out);
}

// round 11
// speedup vs baseline: 8.2090x; 1.0224x over previous
#include <cuda_runtime.h>
#include <cuda_fp16.h>
#include <cstdint>
#include <cstddef>

// Problem constants
#define PB 8
#define PS 1024
#define PE 1024
#define PH 16
#define PD 64
#define PM (PB * PS)        // 8192 GEMM rows
#define PBH (PB * PH)       // 128 (b,h) pairs

// ---------------------------------------------------------------------------
// fp16 scratch (static __device__, allocation-free per harness rules)
// ---------------------------------------------------------------------------
__device__ __half g_xh[PB * PS * PE];     // hidden_states fp16
__device__ __half g_wh[4 * PE * PE];      // wq(*scale*log2e), wk, wv, wo fp16
__device__ __half g_qh[PB * PS * PE];
__device__ __half g_kh[PB * PS * PE];
__device__ __half g_vh[PB * PS * PE];
__device__ __half g_oh[PB * PS * PE];     // attention out (B,H,S,D) fp16

// ---------------------------------------------------------------------------
// PTX helpers
// ---------------------------------------------------------------------------
__device__ __forceinline__ uint32_t smem_u32(const void* p) {
    uint32_t a;
    asm("{ .reg .u64 t; cvta.to.shared.u64 t, %1; cvt.u32.u64 %0, t; }"
        : "=r"(a) : "l"(p));
    return a;
}

// fp16 MMA: D(16x8,f32) += A(16x16,f16) * B(16x8,f16)
__device__ __forceinline__ void mma_f16(float c[4], const uint32_t a[4],
                                        const uint32_t b[2]) {
    asm volatile(
        "mma.sync.aligned.m16n8k16.row.col.f32.f16.f16.f32 "
        "{%0,%1,%2,%3}, {%4,%5,%6,%7}, {%8,%9}, {%0,%1,%2,%3};"
        : "+f"(c[0]), "+f"(c[1]), "+f"(c[2]), "+f"(c[3])
        : "r"(a[0]), "r"(a[1]), "r"(a[2]), "r"(a[3]), "r"(b[0]), "r"(b[1]));
}

#define LDM_X4(r0, r1, r2, r3, addr) \
    asm volatile("ldmatrix.sync.aligned.m8n8.x4.shared.b16 {%0,%1,%2,%3}, [%4];" \
                 : "=r"(r0), "=r"(r1), "=r"(r2), "=r"(r3) : "r"(addr))
#define LDM_X4T(r0, r1, r2, r3, addr) \
    asm volatile("ldmatrix.sync.aligned.m8n8.x4.trans.shared.b16 {%0,%1,%2,%3}, [%4];" \
                 : "=r"(r0), "=r"(r1), "=r"(r2), "=r"(r3) : "r"(addr))

#define CP_ASYNC16(dst, src) \
    asm volatile("cp.async.cg.shared.global [%0], [%1], 16;" \
                 :: "r"(dst), "l"(src) : "memory")
#define CP_COMMIT()  asm volatile("cp.async.commit_group;" ::: "memory")
#define CP_WAIT1()   asm volatile("cp.async.wait_group 1;" ::: "memory")

__device__ __forceinline__ uint32_t f2h2u(float lo, float hi) {
    __half2 h = __floats2half2_rn(lo, hi);
    return *reinterpret_cast<uint32_t*>(&h);
}

__device__ __forceinline__ float ex2(float x) {
    float y;
    asm("ex2.approx.ftz.f32 %0, %1;" : "=f"(y) : "f"(x));
    return y;
}

// ---------------------------------------------------------------------------
// Prepass: fp32 -> fp16 conversion (attention scale * log2e folded into wq)
// ---------------------------------------------------------------------------
__global__ __launch_bounds__(256) void cvt_x(const float* __restrict__ x)
{
    const size_t i = ((size_t)blockIdx.x * 256 + threadIdx.x) * 8;
    const float4 a = *reinterpret_cast<const float4*>(x + i);
    const float4 b = *reinterpret_cast<const float4*>(x + i + 4);
    uint4 u;
    u.x = f2h2u(a.x, a.y); u.y = f2h2u(a.z, a.w);
    u.z = f2h2u(b.x, b.y); u.w = f2h2u(b.z, b.w);
    *reinterpret_cast<uint4*>(g_xh + i) = u;
}

__global__ __launch_bounds__(256) void cvt_w(const float* __restrict__ wq,
                                             const float* __restrict__ wk,
                                             const float* __restrict__ wv,
                                             const float* __restrict__ wo)
{
    const int z = blockIdx.y;
    const float* w = (z == 0) ? wq : (z == 1) ? wk : (z == 2) ? wv : wo;
    // Fold E^-0.5 * log2(e) into Wq: softmax then runs in the exp2 domain.
    const float s = (z == 0) ? 0.03125f * 1.4426950408889634f : 1.0f;
    const size_t i = ((size_t)blockIdx.x * 256 + threadIdx.x) * 8;
    const float4 a = *reinterpret_cast<const float4*>(w + i);
    const float4 b = *reinterpret_cast<const float4*>(w + i + 4);
    uint4 u;
    u.x = f2h2u(a.x * s, a.y * s); u.y = f2h2u(a.z * s, a.w * s);
    u.z = f2h2u(b.x * s, b.y * s); u.w = f2h2u(b.z * s, b.w * s);
    *reinterpret_cast<uint4*>(g_wh + (size_t)z * PE * PE + i) = u;
}

// ---------------------------------------------------------------------------
// fp16 GEMM: C[8192,1024] = A*W (+bias). Block 128x256, KT=64, 8 warps
// (2m x 4n), warp tile 64x64. 3-stage cp.async + double-buffered fragment
// registers (ldmatrix for k16+1 overlaps MMAs for k16).
// PERM=true: A is the (B,H,S,D)->(B,S,E) permuted view of g_oh.
// ---------------------------------------------------------------------------
#define G_AROWB 144
#define G_BROWB 528
#define G_ASTAGE (128 * G_AROWB)            // 18432
#define G_BSTAGE (64 * G_BROWB)             // 33792
#define G_STAGE  (G_ASTAGE + G_BSTAGE)      // 52224
#define GEMM_SMEM_BYTES (3 * G_STAGE)       // 156672

template <bool PERM, bool HALF_OUT>
__device__ __forceinline__ void gemm_body(const __half* __restrict__ Ah,
                                          const __half* __restrict__ Wh,
                                          const float* __restrict__ bias,
                                          __half* __restrict__ Ch,
                                          float* __restrict__ Cf)
{
    extern __shared__ char smraw[];
    const uint32_t sbase = smem_u32(smraw);

    const int tid  = threadIdx.x;            // 256
    const int lane = tid & 31;
    const int wid  = tid >> 5;
    const int m0 = blockIdx.y * 128;
    const int n0 = blockIdx.x * 256;
    const int wr0 = (wid & 1) * 64;
    const int wn0 = (wid >> 1) * 64;
    const int g  = lane >> 2;
    const int t4 = lane & 3;
    const int mat = lane >> 3;
    const int lr  = lane & 7;

    const uint32_t a_off = (uint32_t)((wr0 + (mat & 1) * 8 + lr) * G_AROWB
                                      + (mat >> 1) * 16);
    const uint32_t b_off = (uint32_t)(((mat & 1) * 8 + lr) * G_BROWB
                                      + (wn0 + (mat >> 1) * 8) * 2);

    float c[4][8][4];
#pragma unroll
    for (int mi = 0; mi < 4; mi++)
#pragma unroll
        for (int nj = 0; nj < 8; nj++)
#pragma unroll
            for (int e = 0; e < 4; e++) c[mi][nj][e] = 0.0f;

    auto issue = [&](int s, int kt) {
        const uint32_t As = sbase + (uint32_t)s * G_STAGE;
        const uint32_t Bs = As + G_ASTAGE;
#pragma unroll
        for (int i = 0; i < 4; i++) {
            const int id = i * 256 + tid;
            const int row = id >> 3;
            const int cc = (id & 7) * 8;
            const __half* src;
            if (PERM) {
                const int gm = m0 + row, gk = kt + cc;
                const int bb = gm >> 10, ss = gm & 1023;
                const int hh = gk >> 6,  dd = gk & 63;
                src = Ah + (((size_t)(bb * PH + hh)) * PS + ss) * PD + dd;
            } else {
                src = Ah + (size_t)(m0 + row) * PE + kt + cc;
            }
            CP_ASYNC16(As + row * G_AROWB + cc * 2, src);
        }
#pragma unroll
        for (int i = 0; i < 8; i++) {
            const int id = i * 256 + tid;
            const int row = id >> 5;
            const int cc = (id & 31) * 8;
            CP_ASYNC16(Bs + row * G_BROWB + cc * 2,
                       Wh + (size_t)(kt + row) * PE + n0 + cc);
        }
    };

    issue(0, 0);  CP_COMMIT();
    issue(1, 64); CP_COMMIT();

    uint32_t af[2][4][4], bf[2][8][2];

    for (int it = 0; it < 16; it++) {
        CP_WAIT1();
        __syncthreads();
        if (it + 2 < 16) issue((it + 2) % 3, (it + 2) * 64);
        CP_COMMIT();

        const uint32_t As = sbase + (uint32_t)(it % 3) * G_STAGE;
        const uint32_t Bs = As + G_ASTAGE;

        // Fragment loader for k16-step j (j in 0..3) into buffer b
        auto ldfrag = [&](int b, int j) {
#pragma unroll
            for (int mi = 0; mi < 4; mi++)
                LDM_X4(af[b][mi][0], af[b][mi][1], af[b][mi][2], af[b][mi][3],
                       As + a_off + mi * (16 * G_AROWB) + j * 32);
#pragma unroll
            for (int p = 0; p < 4; p++)
                LDM_X4T(bf[b][2 * p][0], bf[b][2 * p][1],
                        bf[b][2 * p + 1][0], bf[b][2 * p + 1][1],
                        Bs + b_off + j * (16 * G_BROWB) + p * 32);
        };

        ldfrag(0, 0);
#pragma unroll
        for (int j = 0; j < 4; j++) {
            const int cur = j & 1;
            if (j < 3) ldfrag(cur ^ 1, j + 1);   // overlap next frags with MMAs
#pragma unroll
            for (int mi = 0; mi < 4; mi++)
#pragma unroll
                for (int nj = 0; nj < 8; nj++)
                    mma_f16(c[mi][nj], af[cur][mi], bf[cur][nj]);
        }
    }

#pragma unroll
    for (int mi = 0; mi < 4; mi++) {
        const int r = m0 + wr0 + mi * 16 + g;
#pragma unroll
        for (int nj = 0; nj < 8; nj++) {
            const int cg = n0 + wn0 + nj * 8 + 2 * t4;
            if (HALF_OUT) {
                *reinterpret_cast<__half2*>(&Ch[(size_t)r * PE + cg]) =
                    __floats2half2_rn(c[mi][nj][0], c[mi][nj][1]);
                *reinterpret_cast<__half2*>(&Ch[(size_t)(r + 8) * PE + cg]) =
                    __floats2half2_rn(c[mi][nj][2], c[mi][nj][3]);
            } else {
                const float b0 = bias[cg], b1 = bias[cg + 1];
                float2 v0, v1;
                v0.x = c[mi][nj][0] + b0; v0.y = c[mi][nj][1] + b1;
                v1.x = c[mi][nj][2] + b0; v1.y = c[mi][nj][3] + b1;
                *reinterpret_cast<float2*>(&Cf[(size_t)r * PE + cg]) = v0;
                *reinterpret_cast<float2*>(&Cf[(size_t)(r + 8) * PE + cg]) = v1;
            }
        }
    }
}

__global__ __launch_bounds__(256, 1) void qkv_gemm_h()
{
    const int z = blockIdx.z;
    __half* C = (z == 0) ? g_qh : (z == 1) ? g_kh : g_vh;
    gemm_body<false, true>(g_xh, g_wh + (size_t)z * PE * PE, nullptr, C, nullptr);
}

__global__ __launch_bounds__(256, 1) void out_gemm_h(const float* __restrict__ bo,
                                                     float* __restrict__ out)
{
    gemm_body<true, false>(g_oh, g_wh + 3 * (size_t)PE * PE, bo, nullptr, out);
}

// ---------------------------------------------------------------------------
// fp16 flash attention: 4 warps x 32 q-rows (K/V fragments amortized over 2
// m-fragments -> half the ldmatrix traffic of the 8-warp version).
// Br=128, Bc=64, 128 threads. grid (8, 128). Q fragments register-resident.
// P stays in registers (C-frag -> A-frag identity). Softmax in exp2 domain.
// Smem: Qs 18432 + 3 stages x (K 9216 + V 9216) = 73728 B; 2 blocks/SM.
// ---------------------------------------------------------------------------
#define ATT_ROWB 144
#define ATT_KV_STAGE (64 * ATT_ROWB * 2)    // 18432
#define ATT_SMEM_BYTES (18432 + 3 * ATT_KV_STAGE)   // 73728

__global__ __launch_bounds__(128, 2) void flash_attn_h()
{
    extern __shared__ char smraw[];
    const uint32_t sbase = smem_u32(smraw);
    const uint32_t Qs = sbase;

    const int tid  = threadIdx.x;    // 128
    const int lane = tid & 31;
    const int wid  = tid >> 5;       // 0..3 -> q rows wid*32..+31
    const int g  = lane >> 2;
    const int t4 = lane & 3;
    const int mat = lane >> 3;
    const int lr  = lane & 7;
    const int bh = blockIdx.y;
    const int q0 = blockIdx.x * 128;
    const int wr = wid * 32;

    const __half* Qg = g_qh + (size_t)bh * PS * PD;
    const __half* Kg = g_kh + (size_t)bh * PS * PD;
    const __half* Vg = g_vh + (size_t)bh * PS * PD;

    const uint32_t qa_off = (uint32_t)((wr + (mat & 1) * 8 + lr) * ATT_ROWB
                                       + (mat >> 1) * 16);
    const uint32_t kb_off = (uint32_t)(((mat >> 1) * 8 + lr) * ATT_ROWB
                                       + (mat & 1) * 16);
    const uint32_t vb_off = (uint32_t)(((mat & 1) * 8 + lr) * ATT_ROWB
                                       + (mat >> 1) * 16);

    auto issueKV = [&](int s, int t) {
        const uint32_t Ks = sbase + 18432 + (uint32_t)s * ATT_KV_STAGE;
        const uint32_t Vs = Ks + 64 * ATT_ROWB;
#pragma unroll
        for (int i = 0; i < 4; i++) {
            const int id = i * 128 + tid;
            const int row = id >> 3;
            const int cc = (id & 7) * 8;
            CP_ASYNC16(Ks + row * ATT_ROWB + cc * 2,
                       Kg + (size_t)(t * 64 + row) * PD + cc);
            CP_ASYNC16(Vs + row * ATT_ROWB + cc * 2,
                       Vg + (size_t)(t * 64 + row) * PD + cc);
        }
    };

    // Prologue: Q + K/V tile 0 in group 0; K/V tile 1 in group 1
#pragma unroll
    for (int i = 0; i < 8; i++) {
        const int id = i * 128 + tid;
        const int row = id >> 3;
        const int cc = (id & 7) * 8;
        CP_ASYNC16(Qs + row * ATT_ROWB + cc * 2,
                   Qg + (size_t)(q0 + row) * PD + cc);
    }
    issueKV(0, 0); CP_COMMIT();
    issueKV(1, 1); CP_COMMIT();

    // Wait for group 0 (Q + KV0), hoist Q fragments (2 m-frags x 4 k-steps)
    CP_WAIT1();
    __syncthreads();
    uint32_t qf[2][4][4];
#pragma unroll
    for (int mi = 0; mi < 2; mi++)
#pragma unroll
        for (int kk = 0; kk < 4; kk++)
            LDM_X4(qf[mi][kk][0], qf[mi][kk][1], qf[mi][kk][2], qf[mi][kk][3],
                   Qs + qa_off + mi * (16 * ATT_ROWB) + kk * 32);

    float m_i[2][2], l_i[2][2];
#pragma unroll
    for (int mi = 0; mi < 2; mi++) {
        m_i[mi][0] = -1e30f; m_i[mi][1] = -1e30f;
        l_i[mi][0] = 0.0f;   l_i[mi][1] = 0.0f;
    }
    float o[2][8][4];
#pragma unroll
    for (int mi = 0; mi < 2; mi++)
#pragma unroll
        for (int nj = 0; nj < 8; nj++)
#pragma unroll
            for (int e = 0; e < 4; e++) o[mi][nj][e] = 0.0f;

    for (int t = 0; t < 16; t++) {
        if (t > 0) { CP_WAIT1(); __syncthreads(); }
        if (t + 2 < 16) issueKV((t + 2) % 3, t + 2);
        CP_COMMIT();

        const uint32_t Ks = sbase + 18432 + (uint32_t)(t % 3) * ATT_KV_STAGE;
        const uint32_t Vs = Ks + 64 * ATT_ROWB;

        // ---- S = Q Kt : each kf feeds both m-fragments ----
        float s[2][8][4];
#pragma unroll
        for (int mi = 0; mi < 2; mi++)
#pragma unroll
            for (int nj = 0; nj < 8; nj++)
#pragma unroll
                for (int e = 0; e < 4; e++) s[mi][nj][e] = 0.0f;

#pragma unroll
        for (int kk = 0; kk < 4; kk++) {
            uint32_t kf[8][2];
#pragma unroll
            for (int p = 0; p < 4; p++)
                LDM_X4(kf[2 * p][0], kf[2 * p][1], kf[2 * p + 1][0], kf[2 * p + 1][1],
                       Ks + kb_off + p * (16 * ATT_ROWB) + kk * 32);
#pragma unroll
            for (int mi = 0; mi < 2; mi++)
#pragma unroll
                for (int nj = 0; nj < 8; nj++)
                    mma_f16(s[mi][nj], qf[mi][kk], kf[nj]);
        }

        // ---- online softmax in exp2 domain (per m-frag: rows g, g+8) ----
#pragma unroll
        for (int mi = 0; mi < 2; mi++) {
            float mx0 = s[mi][0][0], mx1 = s[mi][0][2];
#pragma unroll
            for (int nj = 0; nj < 8; nj++) {
                mx0 = fmaxf(mx0, fmaxf(s[mi][nj][0], s[mi][nj][1]));
                mx1 = fmaxf(mx1, fmaxf(s[mi][nj][2], s[mi][nj][3]));
            }
#pragma unroll
            for (int off = 1; off <= 2; off <<= 1) {
                mx0 = fmaxf(mx0, __shfl_xor_sync(0xffffffffu, mx0, off));
                mx1 = fmaxf(mx1, __shfl_xor_sync(0xffffffffu, mx1, off));
            }

            const float mn0 = fmaxf(m_i[mi][0], mx0);
            const float mn1 = fmaxf(m_i[mi][1], mx1);
            const float al0 = ex2(m_i[mi][0] - mn0);
            const float al1 = ex2(m_i[mi][1] - mn1);
            m_i[mi][0] = mn0; m_i[mi][1] = mn1;

            float ls0 = 0.0f, ls1 = 0.0f;
#pragma unroll
            for (int nj = 0; nj < 8; nj++) {
                s[mi][nj][0] = ex2(s[mi][nj][0] - mn0);
                s[mi][nj][1] = ex2(s[mi][nj][1] - mn0);
                s[mi][nj][2] = ex2(s[mi][nj][2] - mn1);
                s[mi][nj][3] = ex2(s[mi][nj][3] - mn1);
                ls0 += s[mi][nj][0] + s[mi][nj][1];
                ls1 += s[mi][nj][2] + s[mi][nj][3];
            }
#pragma unroll
            for (int off = 1; off <= 2; off <<= 1) {
                ls0 += __shfl_xor_sync(0xffffffffu, ls0, off);
                ls1 += __shfl_xor_sync(0xffffffffu, ls1, off);
            }
            l_i[mi][0] = l_i[mi][0] * al0 + ls0;
            l_i[mi][1] = l_i[mi][1] * al1 + ls1;

#pragma unroll
            for (int nj = 0; nj < 8; nj++) {
                o[mi][nj][0] *= al0; o[mi][nj][1] *= al0;
                o[mi][nj][2] *= al1; o[mi][nj][3] *= al1;
            }
        }

        // ---- O += P V : P converts C-frag -> A-frag in registers;
        //      each vf feeds both m-fragments ----
#pragma unroll
        for (int kk = 0; kk < 4; kk++) {
            uint32_t vf[8][2];
#pragma unroll
            for (int p = 0; p < 4; p++)
                LDM_X4T(vf[2 * p][0], vf[2 * p][1], vf[2 * p + 1][0], vf[2 * p + 1][1],
                        Vs + vb_off + kk * (16 * ATT_ROWB) + p * 32);
#pragma unroll
            for (int mi = 0; mi < 2; mi++) {
                uint32_t pf[4];
                pf[0] = f2h2u(s[mi][2 * kk][0],     s[mi][2 * kk][1]);
                pf[1] = f2h2u(s[mi][2 * kk][2],     s[mi][2 * kk][3]);
                pf[2] = f2h2u(s[mi][2 * kk + 1][0], s[mi][2 * kk + 1][1]);
                pf[3] = f2h2u(s[mi][2 * kk + 1][2], s[mi][2 * kk + 1][3]);
#pragma unroll
                for (int nj = 0; nj < 8; nj++)
                    mma_f16(o[mi][nj], pf, vf[nj]);
            }
        }
    }

    // ---- epilogue: normalize, fp16 store to g_oh ----
    __half* Op = g_oh + (size_t)bh * PS * PD;
#pragma unroll
    for (int mi = 0; mi < 2; mi++) {
        const float inv0 = 1.0f / l_i[mi][0];
        const float inv1 = 1.0f / l_i[mi][1];
        const int r0 = q0 + wr + mi * 16 + g;
#pragma unroll
        for (int nj = 0; nj < 8; nj++) {
            const int cg = nj * 8 + 2 * t4;
            *reinterpret_cast<__half2*>(&Op[(size_t)r0 * PD + cg]) =
                __floats2half2_rn(o[mi][nj][0] * inv0, o[mi][nj][1] * inv0);
            *reinterpret_cast<__half2*>(&Op[(size_t)(r0 + 8) * PD + cg]) =
                __floats2half2_rn(o[mi][nj][2] * inv1, o[mi][nj][3] * inv1);
        }
    }
}

// ---------------------------------------------------------------------------
// kernel_launch
// ---------------------------------------------------------------------------
extern "C" void kernel_launch(void* const* d_in, const int* in_sizes, int n_in,
                              void* d_out, int out_size)
{
    const float* hidden = (const float*)d_in[0];
    const float* wq = (const float*)d_in[1];
    const float* wk = (const float*)d_in[2];
    const float* wv = (const float*)d_in[3];
    const float* wo = (const float*)d_in[4];
    const float* bo = (const float*)d_in[5];
    float* out = (float*)d_out;
    (void)in_sizes; (void)n_in; (void)out_size;

    cudaFuncSetAttribute(qkv_gemm_h, cudaFuncAttributeMaxDynamicSharedMemorySize,
                         GEMM_SMEM_BYTES);
    cudaFuncSetAttribute(out_gemm_h, cudaFuncAttributeMaxDynamicSharedMemorySize,
                         GEMM_SMEM_BYTES);
    cudaFuncSetAttribute(flash_attn_h, cudaFuncAttributeMaxDynamicSharedMemorySize,
                         ATT_SMEM_BYTES);

    // Prepass: fp32 -> fp16 (scale * log2e folded into Wq)
    cvt_x<<<(PB * PS * PE) / (256 * 8), 256>>>(hidden);
    cvt_w<<<dim3((PE * PE) / (256 * 8), 4), 256>>>(wq, wk, wv, wo);

    // QKV projections (fp16 mma, cp.async 3-stage, fragment double-buffer)
    qkv_gemm_h<<<dim3(PE / 256, PM / 128, 3), 256, GEMM_SMEM_BYTES>>>();

    // Attention (fp16 mma flash, 4 warps x 32 rows, register P)
    flash_attn_h<<<dim3(PS / 128, PBH), 128, ATT_SMEM_BYTES>>>();

    // Output projection (fp16 mma) + fp32 bias/out
    out_gemm_h<<<dim3(PE / 256, PM / 128, 1), 256, GEMM_SMEM_BYTES>>>(bo, out);
}

// round 14
// speedup vs baseline: 9.0141x; 1.0981x over previous
#include <cuda_runtime.h>
#include <cuda_fp16.h>
#include <cstdint>
#include <cstddef>

// Problem constants
#define PB 8
#define PS 1024
#define PE 1024
#define PH 16
#define PD 64
#define PM (PB * PS)        // 8192 GEMM rows
#define PBH (PB * PH)       // 128 (b,h) pairs

// ---------------------------------------------------------------------------
// fp16 scratch (static __device__, allocation-free per harness rules)
// ---------------------------------------------------------------------------
__device__ __half g_xh[PB * PS * PE];     // hidden_states fp16
__device__ __half g_wh[4 * PE * PE];      // wq(*scale*log2e), wk, wv, wo fp16
__device__ __half g_qh[PB * PS * PE];
__device__ __half g_kh[PB * PS * PE];
__device__ __half g_vh[PB * PS * PE];
__device__ __half g_oh[PB * PS * PE];     // attention out (B,H,S,D) fp16

// ---------------------------------------------------------------------------
// PTX helpers
// ---------------------------------------------------------------------------
__device__ __forceinline__ uint32_t smem_u32(const void* p) {
    uint32_t a;
    asm("{ .reg .u64 t; cvta.to.shared.u64 t, %1; cvt.u32.u64 %0, t; }"
        : "=r"(a) : "l"(p));
    return a;
}

// fp16 MMA: D(16x8,f32) += A(16x16,f16) * B(16x8,f16)
__device__ __forceinline__ void mma_f16(float c[4], const uint32_t a[4],
                                        const uint32_t b[2]) {
    asm volatile(
        "mma.sync.aligned.m16n8k16.row.col.f32.f16.f16.f32 "
        "{%0,%1,%2,%3}, {%4,%5,%6,%7}, {%8,%9}, {%0,%1,%2,%3};"
        : "+f"(c[0]), "+f"(c[1]), "+f"(c[2]), "+f"(c[3])
        : "r"(a[0]), "r"(a[1]), "r"(a[2]), "r"(a[3]), "r"(b[0]), "r"(b[1]));
}

#define LDM_X4(r0, r1, r2, r3, addr) \
    asm volatile("ldmatrix.sync.aligned.m8n8.x4.shared.b16 {%0,%1,%2,%3}, [%4];" \
                 : "=r"(r0), "=r"(r1), "=r"(r2), "=r"(r3) : "r"(addr))
#define LDM_X4T(r0, r1, r2, r3, addr) \
    asm volatile("ldmatrix.sync.aligned.m8n8.x4.trans.shared.b16 {%0,%1,%2,%3}, [%4];" \
                 : "=r"(r0), "=r"(r1), "=r"(r2), "=r"(r3) : "r"(addr))

#define CP_ASYNC16(dst, src) \
    asm volatile("cp.async.cg.shared.global [%0], [%1], 16;" \
                 :: "r"(dst), "l"(src) : "memory")
#define CP_COMMIT()  asm volatile("cp.async.commit_group;" ::: "memory")
#define CP_WAIT1()   asm volatile("cp.async.wait_group 1;" ::: "memory")

__device__ __forceinline__ uint32_t f2h2u(float lo, float hi) {
    __half2 h = __floats2half2_rn(lo, hi);
    return *reinterpret_cast<uint32_t*>(&h);
}

__device__ __forceinline__ float ex2(float x) {
    float y;
    asm("ex2.approx.ftz.f32 %0, %1;" : "=f"(y) : "f"(x));
    return y;
}

// ---------------------------------------------------------------------------
// Prepass: fp32 -> fp16 conversion (attention scale * log2e folded into wq)
// ---------------------------------------------------------------------------
__global__ __launch_bounds__(256) void cvt_x(const float* __restrict__ x)
{
    const size_t i = ((size_t)blockIdx.x * 256 + threadIdx.x) * 8;
    const float4 a = *reinterpret_cast<const float4*>(x + i);
    const float4 b = *reinterpret_cast<const float4*>(x + i + 4);
    uint4 u;
    u.x = f2h2u(a.x, a.y); u.y = f2h2u(a.z, a.w);
    u.z = f2h2u(b.x, b.y); u.w = f2h2u(b.z, b.w);
    *reinterpret_cast<uint4*>(g_xh + i) = u;
}

__global__ __launch_bounds__(256) void cvt_w(const float* __restrict__ wq,
                                             const float* __restrict__ wk,
                                             const float* __restrict__ wv,
                                             const float* __restrict__ wo)
{
    const int z = blockIdx.y;
    const float* w = (z == 0) ? wq : (z == 1) ? wk : (z == 2) ? wv : wo;
    // Fold E^-0.5 * log2(e) into Wq: softmax then runs in the exp2 domain.
    const float s = (z == 0) ? 0.03125f * 1.4426950408889634f : 1.0f;
    const size_t i = ((size_t)blockIdx.x * 256 + threadIdx.x) * 8;
    const float4 a = *reinterpret_cast<const float4*>(w + i);
    const float4 b = *reinterpret_cast<const float4*>(w + i + 4);
    uint4 u;
    u.x = f2h2u(a.x * s, a.y * s); u.y = f2h2u(a.z * s, a.w * s);
    u.z = f2h2u(b.x * s, b.y * s); u.w = f2h2u(b.z * s, b.w * s);
    *reinterpret_cast<uint4*>(g_wh + (size_t)z * PE * PE + i) = u;
}

// ---------------------------------------------------------------------------
// fp16 GEMM: C[8192,1024] = A*W (+bias). Block tile 128x128, KT=64,
// 128 threads = 4 warps (2m x 2n), warp tile 64x64. 3-stage cp.async.
// Small block => 2 blocks/SM (16 warps/SM) for latency hiding.
// A smem row = 64 halves + pad = 144 B; B smem row = 128 halves + pad = 272 B
// (both ≡ 4 words mod 32 -> conflict-free ldmatrix phases).
// Stage = 128*144 + 64*272 = 35840 B; 3 stages = 107520 B.
// PERM=true: A is the (B,H,S,D)->(B,S,E) permuted view of g_oh.
// ---------------------------------------------------------------------------
#define G_AROWB 144
#define G_BROWB 272
#define G_ASTAGE (128 * G_AROWB)            // 18432
#define G_BSTAGE (64 * G_BROWB)             // 17408
#define G_STAGE  (G_ASTAGE + G_BSTAGE)      // 35840
#define GEMM_SMEM_BYTES (3 * G_STAGE)       // 107520

template <bool PERM, bool HALF_OUT>
__device__ __forceinline__ void gemm_body(const __half* __restrict__ Ah,
                                          const __half* __restrict__ Wh,
                                          const float* __restrict__ bias,
                                          __half* __restrict__ Ch,
                                          float* __restrict__ Cf)
{
    extern __shared__ char smraw[];
    const uint32_t sbase = smem_u32(smraw);

    const int tid  = threadIdx.x;            // 128
    const int lane = tid & 31;
    const int wid  = tid >> 5;               // 0..3
    const int m0 = blockIdx.y * 128;
    const int n0 = blockIdx.x * 128;
    const int wr0 = (wid & 1) * 64;
    const int wn0 = (wid >> 1) * 64;
    const int g  = lane >> 2;
    const int t4 = lane & 3;
    const int mat = lane >> 3;
    const int lr  = lane & 7;

    const uint32_t a_off = (uint32_t)((wr0 + (mat & 1) * 8 + lr) * G_AROWB
                                      + (mat >> 1) * 16);
    const uint32_t b_off = (uint32_t)(((mat & 1) * 8 + lr) * G_BROWB
                                      + (wn0 + (mat >> 1) * 8) * 2);

    float c[4][8][4];
#pragma unroll
    for (int mi = 0; mi < 4; mi++)
#pragma unroll
        for (int nj = 0; nj < 8; nj++)
#pragma unroll
            for (int e = 0; e < 4; e++) c[mi][nj][e] = 0.0f;

    auto issue = [&](int s, int kt) {
        const uint32_t As = sbase + (uint32_t)s * G_STAGE;
        const uint32_t Bs = As + G_ASTAGE;
        // A: 128 rows x 8 chunks (8 halves = 16B each) = 1024 -> 8 iters
#pragma unroll
        for (int i = 0; i < 8; i++) {
            const int id = i * 128 + tid;
            const int row = id >> 3;             // 0..127
            const int cc = (id & 7) * 8;         // halves offset in k (0..56)
            const __half* src;
            if (PERM) {
                const int gm = m0 + row, gk = kt + cc;
                const int bb = gm >> 10, ss = gm & 1023;
                const int hh = gk >> 6,  dd = gk & 63;
                src = Ah + (((size_t)(bb * PH + hh)) * PS + ss) * PD + dd;
            } else {
                src = Ah + (size_t)(m0 + row) * PE + kt + cc;
            }
            CP_ASYNC16(As + row * G_AROWB + cc * 2, src);
        }
        // B: 64 rows x 16 chunks = 1024 -> 8 iters
#pragma unroll
        for (int i = 0; i < 8; i++) {
            const int id = i * 128 + tid;
            const int row = id >> 4;             // 0..63
            const int cc = (id & 15) * 8;        // halves offset in n
            CP_ASYNC16(Bs + row * G_BROWB + cc * 2,
                       Wh + (size_t)(kt + row) * PE + n0 + cc);
        }
    };

    issue(0, 0);  CP_COMMIT();
    issue(1, 64); CP_COMMIT();

    for (int it = 0; it < 16; it++) {
        CP_WAIT1();
        __syncthreads();
        if (it + 2 < 16) issue((it + 2) % 3, (it + 2) * 64);
        CP_COMMIT();

        const uint32_t As = sbase + (uint32_t)(it % 3) * G_STAGE;
        const uint32_t Bs = As + G_ASTAGE;

#pragma unroll
        for (int j = 0; j < 4; j++) {
            uint32_t af[4][4], bf[8][2];
#pragma unroll
            for (int mi = 0; mi < 4; mi++)
                LDM_X4(af[mi][0], af[mi][1], af[mi][2], af[mi][3],
                       As + a_off + mi * (16 * G_AROWB) + j * 32);
#pragma unroll
            for (int p = 0; p < 4; p++)
                LDM_X4T(bf[2 * p][0], bf[2 * p][1],
                        bf[2 * p + 1][0], bf[2 * p + 1][1],
                        Bs + b_off + j * (16 * G_BROWB) + p * 32);
#pragma unroll
            for (int mi = 0; mi < 4; mi++)
#pragma unroll
                for (int nj = 0; nj < 8; nj++)
                    mma_f16(c[mi][nj], af[mi], bf[nj]);
        }
    }

#pragma unroll
    for (int mi = 0; mi < 4; mi++) {
        const int r = m0 + wr0 + mi * 16 + g;
#pragma unroll
        for (int nj = 0; nj < 8; nj++) {
            const int cg = n0 + wn0 + nj * 8 + 2 * t4;
            if (HALF_OUT) {
                *reinterpret_cast<__half2*>(&Ch[(size_t)r * PE + cg]) =
                    __floats2half2_rn(c[mi][nj][0], c[mi][nj][1]);
                *reinterpret_cast<__half2*>(&Ch[(size_t)(r + 8) * PE + cg]) =
                    __floats2half2_rn(c[mi][nj][2], c[mi][nj][3]);
            } else {
                const float b0 = bias[cg], b1 = bias[cg + 1];
                float2 v0, v1;
                v0.x = c[mi][nj][0] + b0; v0.y = c[mi][nj][1] + b1;
                v1.x = c[mi][nj][2] + b0; v1.y = c[mi][nj][3] + b1;
                *reinterpret_cast<float2*>(&Cf[(size_t)r * PE + cg]) = v0;
                *reinterpret_cast<float2*>(&Cf[(size_t)(r + 8) * PE + cg]) = v1;
            }
        }
    }
}

__global__ __launch_bounds__(128, 2) void qkv_gemm_h()
{
    const int z = blockIdx.z;
    __half* C = (z == 0) ? g_qh : (z == 1) ? g_kh : g_vh;
    gemm_body<false, true>(g_xh, g_wh + (size_t)z * PE * PE, nullptr, C, nullptr);
}

__global__ __launch_bounds__(128, 2) void out_gemm_h(const float* __restrict__ bo,
                                                     float* __restrict__ out)
{
    gemm_body<true, false>(g_oh, g_wh + 3 * (size_t)PE * PE, bo, nullptr, out);
}

// ---------------------------------------------------------------------------
// fp16 flash attention (unchanged from R11): 4 warps x 32 q-rows, Br=128,
// Bc=64, 128 threads, grid (8, 128). Q fragments register-resident; P stays
// in registers (C-frag -> A-frag identity); softmax in exp2 domain.
// Smem: Qs 18432 + 3 stages x (K 9216 + V 9216) = 73728 B.
// ---------------------------------------------------------------------------
#define ATT_ROWB 144
#define ATT_KV_STAGE (64 * ATT_ROWB * 2)    // 18432
#define ATT_SMEM_BYTES (18432 + 3 * ATT_KV_STAGE)   // 73728

__global__ __launch_bounds__(128, 2) void flash_attn_h()
{
    extern __shared__ char smraw[];
    const uint32_t sbase = smem_u32(smraw);
    const uint32_t Qs = sbase;

    const int tid  = threadIdx.x;    // 128
    const int lane = tid & 31;
    const int wid  = tid >> 5;       // 0..3 -> q rows wid*32..+31
    const int g  = lane >> 2;
    const int t4 = lane & 3;
    const int mat = lane >> 3;
    const int lr  = lane & 7;
    const int bh = blockIdx.y;
    const int q0 = blockIdx.x * 128;
    const int wr = wid * 32;

    const __half* Qg = g_qh + (size_t)bh * PS * PD;
    const __half* Kg = g_kh + (size_t)bh * PS * PD;
    const __half* Vg = g_vh + (size_t)bh * PS * PD;

    const uint32_t qa_off = (uint32_t)((wr + (mat & 1) * 8 + lr) * ATT_ROWB
                                       + (mat >> 1) * 16);
    const uint32_t kb_off = (uint32_t)(((mat >> 1) * 8 + lr) * ATT_ROWB
                                       + (mat & 1) * 16);
    const uint32_t vb_off = (uint32_t)(((mat & 1) * 8 + lr) * ATT_ROWB
                                       + (mat >> 1) * 16);

    auto issueKV = [&](int s, int t) {
        const uint32_t Ks = sbase + 18432 + (uint32_t)s * ATT_KV_STAGE;
        const uint32_t Vs = Ks + 64 * ATT_ROWB;
#pragma unroll
        for (int i = 0; i < 4; i++) {
            const int id = i * 128 + tid;
            const int row = id >> 3;
            const int cc = (id & 7) * 8;
            CP_ASYNC16(Ks + row * ATT_ROWB + cc * 2,
                       Kg + (size_t)(t * 64 + row) * PD + cc);
            CP_ASYNC16(Vs + row * ATT_ROWB + cc * 2,
                       Vg + (size_t)(t * 64 + row) * PD + cc);
        }
    };

    // Prologue: Q + K/V tile 0 in group 0; K/V tile 1 in group 1
#pragma unroll
    for (int i = 0; i < 8; i++) {
        const int id = i * 128 + tid;
        const int row = id >> 3;
        const int cc = (id & 7) * 8;
        CP_ASYNC16(Qs + row * ATT_ROWB + cc * 2,
                   Qg + (size_t)(q0 + row) * PD + cc);
    }
    issueKV(0, 0); CP_COMMIT();
    issueKV(1, 1); CP_COMMIT();

    // Wait for group 0 (Q + KV0), hoist Q fragments (2 m-frags x 4 k-steps)
    CP_WAIT1();
    __syncthreads();
    uint32_t qf[2][4][4];
#pragma unroll
    for (int mi = 0; mi < 2; mi++)
#pragma unroll
        for (int kk = 0; kk < 4; kk++)
            LDM_X4(qf[mi][kk][0], qf[mi][kk][1], qf[mi][kk][2], qf[mi][kk][3],
                   Qs + qa_off + mi * (16 * ATT_ROWB) + kk * 32);

    float m_i[2][2], l_i[2][2];
#pragma unroll
    for (int mi = 0; mi < 2; mi++) {
        m_i[mi][0] = -1e30f; m_i[mi][1] = -1e30f;
        l_i[mi][0] = 0.0f;   l_i[mi][1] = 0.0f;
    }
    float o[2][8][4];
#pragma unroll
    for (int mi = 0; mi < 2; mi++)
#pragma unroll
        for (int nj = 0; nj < 8; nj++)
#pragma unroll
            for (int e = 0; e < 4; e++) o[mi][nj][e] = 0.0f;

    for (int t = 0; t < 16; t++) {
        if (t > 0) { CP_WAIT1(); __syncthreads(); }
        if (t + 2 < 16) issueKV((t + 2) % 3, t + 2);
        CP_COMMIT();

        const uint32_t Ks = sbase + 18432 + (uint32_t)(t % 3) * ATT_KV_STAGE;
        const uint32_t Vs = Ks + 64 * ATT_ROWB;

        // ---- S = Q Kt : each kf feeds both m-fragments ----
        float s[2][8][4];
#pragma unroll
        for (int mi = 0; mi < 2; mi++)
#pragma unroll
            for (int nj = 0; nj < 8; nj++)
#pragma unroll
                for (int e = 0; e < 4; e++) s[mi][nj][e] = 0.0f;

#pragma unroll
        for (int kk = 0; kk < 4; kk++) {
            uint32_t kf[8][2];
#pragma unroll
            for (int p = 0; p < 4; p++)
                LDM_X4(kf[2 * p][0], kf[2 * p][1], kf[2 * p + 1][0], kf[2 * p + 1][1],
                       Ks + kb_off + p * (16 * ATT_ROWB) + kk * 32);
#pragma unroll
            for (int mi = 0; mi < 2; mi++)
#pragma unroll
                for (int nj = 0; nj < 8; nj++)
                    mma_f16(s[mi][nj], qf[mi][kk], kf[nj]);
        }

        // ---- online softmax in exp2 domain (per m-frag: rows g, g+8) ----
#pragma unroll
        for (int mi = 0; mi < 2; mi++) {
            float mx0 = s[mi][0][0], mx1 = s[mi][0][2];
#pragma unroll
            for (int nj = 0; nj < 8; nj++) {
                mx0 = fmaxf(mx0, fmaxf(s[mi][nj][0], s[mi][nj][1]));
                mx1 = fmaxf(mx1, fmaxf(s[mi][nj][2], s[mi][nj][3]));
            }
#pragma unroll
            for (int off = 1; off <= 2; off <<= 1) {
                mx0 = fmaxf(mx0, __shfl_xor_sync(0xffffffffu, mx0, off));
                mx1 = fmaxf(mx1, __shfl_xor_sync(0xffffffffu, mx1, off));
            }

            const float mn0 = fmaxf(m_i[mi][0], mx0);
            const float mn1 = fmaxf(m_i[mi][1], mx1);
            const float al0 = ex2(m_i[mi][0] - mn0);
            const float al1 = ex2(m_i[mi][1] - mn1);
            m_i[mi][0] = mn0; m_i[mi][1] = mn1;

            float ls0 = 0.0f, ls1 = 0.0f;
#pragma unroll
            for (int nj = 0; nj < 8; nj++) {
                s[mi][nj][0] = ex2(s[mi][nj][0] - mn0);
                s[mi][nj][1] = ex2(s[mi][nj][1] - mn0);
                s[mi][nj][2] = ex2(s[mi][nj][2] - mn1);
                s[mi][nj][3] = ex2(s[mi][nj][3] - mn1);
                ls0 += s[mi][nj][0] + s[mi][nj][1];
                ls1 += s[mi][nj][2] + s[mi][nj][3];
            }
#pragma unroll
            for (int off = 1; off <= 2; off <<= 1) {
                ls0 += __shfl_xor_sync(0xffffffffu, ls0, off);
                ls1 += __shfl_xor_sync(0xffffffffu, ls1, off);
            }
            l_i[mi][0] = l_i[mi][0] * al0 + ls0;
            l_i[mi][1] = l_i[mi][1] * al1 + ls1;

#pragma unroll
            for (int nj = 0; nj < 8; nj++) {
                o[mi][nj][0] *= al0; o[mi][nj][1] *= al0;
                o[mi][nj][2] *= al1; o[mi][nj][3] *= al1;
            }
        }

        // ---- O += P V : P converts C-frag -> A-frag in registers;
        //      each vf feeds both m-fragments ----
#pragma unroll
        for (int kk = 0; kk < 4; kk++) {
            uint32_t vf[8][2];
#pragma unroll
            for (int p = 0; p < 4; p++)
                LDM_X4T(vf[2 * p][0], vf[2 * p][1], vf[2 * p + 1][0], vf[2 * p + 1][1],
                        Vs + vb_off + kk * (16 * ATT_ROWB) + p * 32);
#pragma unroll
            for (int mi = 0; mi < 2; mi++) {
                uint32_t pf[4];
                pf[0] = f2h2u(s[mi][2 * kk][0],     s[mi][2 * kk][1]);
                pf[1] = f2h2u(s[mi][2 * kk][2],     s[mi][2 * kk][3]);
                pf[2] = f2h2u(s[mi][2 * kk + 1][0], s[mi][2 * kk + 1][1]);
                pf[3] = f2h2u(s[mi][2 * kk + 1][2], s[mi][2 * kk + 1][3]);
#pragma unroll
                for (int nj = 0; nj < 8; nj++)
                    mma_f16(o[mi][nj], pf, vf[nj]);
            }
        }
    }

    // ---- epilogue: normalize, fp16 store to g_oh ----
    __half* Op = g_oh + (size_t)bh * PS * PD;
#pragma unroll
    for (int mi = 0; mi < 2; mi++) {
        const float inv0 = 1.0f / l_i[mi][0];
        const float inv1 = 1.0f / l_i[mi][1];
        const int r0 = q0 + wr + mi * 16 + g;
#pragma unroll
        for (int nj = 0; nj < 8; nj++) {
            const int cg = nj * 8 + 2 * t4;
            *reinterpret_cast<__half2*>(&Op[(size_t)r0 * PD + cg]) =
                __floats2half2_rn(o[mi][nj][0] * inv0, o[mi][nj][1] * inv0);
            *reinterpret_cast<__half2*>(&Op[(size_t)(r0 + 8) * PD + cg]) =
                __floats2half2_rn(o[mi][nj][2] * inv1, o[mi][nj][3] * inv1);
        }
    }
}

// ---------------------------------------------------------------------------
// kernel_launch
// ---------------------------------------------------------------------------
extern "C" void kernel_launch(void* const* d_in, const int* in_sizes, int n_in,
                              void* d_out, int out_size)
{
    const float* hidden = (const float*)d_in[0];
    const float* wq = (const float*)d_in[1];
    const float* wk = (const float*)d_in[2];
    const float* wv = (const float*)d_in[3];
    const float* wo = (const float*)d_in[4];
    const float* bo = (const float*)d_in[5];
    float* out = (float*)d_out;
    (void)in_sizes; (void)n_in; (void)out_size;

    cudaFuncSetAttribute(qkv_gemm_h, cudaFuncAttributeMaxDynamicSharedMemorySize,
                         GEMM_SMEM_BYTES);
    cudaFuncSetAttribute(out_gemm_h, cudaFuncAttributeMaxDynamicSharedMemorySize,
                         GEMM_SMEM_BYTES);
    cudaFuncSetAttribute(flash_attn_h, cudaFuncAttributeMaxDynamicSharedMemorySize,
                         ATT_SMEM_BYTES);

    // Prepass: fp32 -> fp16 (scale * log2e folded into Wq)
    cvt_x<<<(PB * PS * PE) / (256 * 8), 256>>>(hidden);
    cvt_w<<<dim3((PE * PE) / (256 * 8), 4), 256>>>(wq, wk, wv, wo);

    // QKV projections (fp16 mma, 128-thread blocks, 2 blocks/SM)
    qkv_gemm_h<<<dim3(PE / 128, PM / 128, 3), 128, GEMM_SMEM_BYTES>>>();

    // Attention (fp16 mma flash, 4 warps x 32 rows, register P)
    flash_attn_h<<<dim3(PS / 128, PBH), 128, ATT_SMEM_BYTES>>>();

    // Output projection (fp16 mma) + fp32 bias/out
    out_gemm_h<<<dim3(PE / 128, PM / 128, 1), 128, GEMM_SMEM_BYTES>>>(bo, out);
}